// round 1
// baseline (speedup 1.0000x reference)
#include <cuda_runtime.h>
#include <cuda_bf16.h>
#include <math.h>

// ---------------- problem constants ----------------
#define BATCH   2
#define SEQLEN  512
#define DMODEL  1024
#define DINNER  2048
#define NHEADS  32
#define HEADDIM 64
#define DSTATE  128
#define DCONV   4
#define DPROJ   4384   // 2*DINNER + 2*DSTATE + NHEADS
#define CONVD   2304   // DINNER + 2*DSTATE
#define MROWS   (BATCH*SEQLEN)   // 1024
#define DT_OFF  (DINNER + CONVD) // 4352

// ---------------- scratch (static device memory; no allocs allowed) -------
__device__ float g_zx [MROWS * DPROJ];   // in_proj output  (1024 x 4384)
__device__ float g_xbc[MROWS * CONVD];   // conv+silu output (1024 x 2304)
__device__ float g_y  [MROWS * DINNER];  // scan output
__device__ float g_yn [MROWS * DINNER];  // normed output

// =====================================================================
// SGEMM  C[m,n] = sum_k A[m,k] * B[n,k]     (NT, both K-contiguous)
// 128x128 block tile, BK=8, 256 threads, 8x8 per thread
// M must be a multiple of 128, K a multiple of 8; N is bound-checked.
// =====================================================================
#define BM 128
#define BN 128
#define BKQ 8
#define TM 8
#define TN 8

__global__ __launch_bounds__(256) void sgemm_nt(
    const float* __restrict__ A, const float* __restrict__ Bm,
    float* __restrict__ C, int M, int N, int K)
{
    __shared__ float As[BKQ][BM];
    __shared__ float Bs[BKQ][BN];

    const int tid = threadIdx.x;
    const int m0 = blockIdx.y * BM;
    const int n0 = blockIdx.x * BN;

    const int tm = (tid >> 4) * TM;    // 0..120
    const int tn = (tid & 15) * TN;    // 0..120

    const int lrow = tid >> 1;         // 0..127
    const int lcol = (tid & 1) * 4;    // 0 or 4

    float acc[TM][TN];
#pragma unroll
    for (int i = 0; i < TM; i++)
#pragma unroll
        for (int j = 0; j < TN; j++) acc[i][j] = 0.f;

    const float* Aptr = A + (size_t)(m0 + lrow) * K + lcol;
    const bool   bok  = (n0 + lrow) < N;
    const float* Bptr = Bm + (size_t)(n0 + lrow) * K + lcol;

    for (int k0 = 0; k0 < K; k0 += BKQ) {
        float4 av = *reinterpret_cast<const float4*>(Aptr + k0);
        float4 bv = bok ? *reinterpret_cast<const float4*>(Bptr + k0)
                        : make_float4(0.f, 0.f, 0.f, 0.f);
        __syncthreads();
        As[lcol + 0][lrow] = av.x;
        As[lcol + 1][lrow] = av.y;
        As[lcol + 2][lrow] = av.z;
        As[lcol + 3][lrow] = av.w;
        Bs[lcol + 0][lrow] = bv.x;
        Bs[lcol + 1][lrow] = bv.y;
        Bs[lcol + 2][lrow] = bv.z;
        Bs[lcol + 3][lrow] = bv.w;
        __syncthreads();

#pragma unroll
        for (int k = 0; k < BKQ; k++) {
            float4 a0 = *reinterpret_cast<const float4*>(&As[k][tm]);
            float4 a1 = *reinterpret_cast<const float4*>(&As[k][tm + 4]);
            float4 b0 = *reinterpret_cast<const float4*>(&Bs[k][tn]);
            float4 b1 = *reinterpret_cast<const float4*>(&Bs[k][tn + 4]);
            float ra[8] = {a0.x, a0.y, a0.z, a0.w, a1.x, a1.y, a1.z, a1.w};
            float rb[8] = {b0.x, b0.y, b0.z, b0.w, b1.x, b1.y, b1.z, b1.w};
#pragma unroll
            for (int i = 0; i < TM; i++)
#pragma unroll
                for (int j = 0; j < TN; j++)
                    acc[i][j] = fmaf(ra[i], rb[j], acc[i][j]);
        }
    }

#pragma unroll
    for (int i = 0; i < TM; i++) {
        float* crow = C + (size_t)(m0 + tm + i) * N + n0 + tn;
#pragma unroll
        for (int j = 0; j < TN; j++) {
            if (n0 + tn + j < N) crow[j] = acc[i][j];
        }
    }
}

// =====================================================================
// Depthwise causal conv (k=4) + bias + SiLU over the xBC slice of zx
// =====================================================================
__global__ __launch_bounds__(256) void conv_silu_kernel(
    const float* __restrict__ cw, const float* __restrict__ cb)
{
    int idx = blockIdx.x * blockDim.x + threadIdx.x;
    if (idx >= MROWS * CONVD) return;
    int c = idx % CONVD;
    int l = (idx / CONVD) % SEQLEN;
    int b = idx / (CONVD * SEQLEN);

    float acc = cb[c];
    const float* w = cw + c * DCONV;
#pragma unroll
    for (int j = 0; j < DCONV; j++) {
        int ls = l - (DCONV - 1) + j;
        if (ls >= 0)
            acc = fmaf(w[j], g_zx[(size_t)(b * SEQLEN + ls) * DPROJ + DINNER + c], acc);
    }
    // silu
    g_xbc[idx] = acc / (1.f + expf(-acc));
}

// =====================================================================
// Sequential SSM scan. One block per (batch, head). 256 threads.
// thread t: p = t&63 (headdim), nb = t>>6 (state chunk), owns s[32] regs.
// =====================================================================
__global__ __launch_bounds__(256) void ssm_scan_kernel(
    const float* __restrict__ dt_bias, const float* __restrict__ A_log,
    const float* __restrict__ Dp)
{
    const int b = blockIdx.x >> 5;   // NHEADS = 32
    const int h = blockIdx.x & 31;
    const int tid = threadIdx.x;
    const int p = tid & 63;
    const int nbase = (tid >> 6) * 32;

    __shared__ float sh_in[320];   // [0:64) x, [64:192) B, [192:320) C
    __shared__ float sh_red[256];

    float s[32];
#pragma unroll
    for (int i = 0; i < 32; i++) s[i] = 0.f;

    const float Aval = -expf(A_log[h]);
    const float dtb  = dt_bias[h];
    const float Dv   = Dp[h];

    for (int l = 0; l < SEQLEN; l++) {
        const size_t row = (size_t)(b * SEQLEN + l);
        const float* xrow = g_xbc + row * CONVD;
        if (tid < 64) sh_in[tid] = xrow[h * HEADDIM + tid];
        sh_in[64 + tid] = xrow[DINNER + tid];   // B (128) then C (128)

        float dtr = g_zx[row * DPROJ + DT_OFF + h] + dtb;
        float dt  = (dtr > 20.f) ? dtr : log1pf(expf(dtr));
        float dA  = expf(dt * Aval);
        __syncthreads();

        float coef = dt * sh_in[p];
        float acc = 0.f;
#pragma unroll
        for (int i = 0; i < 32; i++) {
            float Bn = sh_in[64 + nbase + i];
            float Cn = sh_in[192 + nbase + i];
            s[i] = fmaf(s[i], dA, coef * Bn);
            acc = fmaf(s[i], Cn, acc);
        }
        sh_red[tid] = acc;
        __syncthreads();
        if (tid < 64) {
            float yv = sh_red[tid] + sh_red[tid + 64] + sh_red[tid + 128] +
                       sh_red[tid + 192] + Dv * sh_in[tid];
            g_y[row * DINNER + h * HEADDIM + tid] = yv;
        }
        __syncthreads();
    }
}

// =====================================================================
// Gated RMSNorm: yg = y * silu(z); yn = yg * rsqrt(mean(yg^2)+eps) * w
// One block per row (b*L). 256 threads, 8 channels each.
// =====================================================================
__global__ __launch_bounds__(256) void gated_norm_kernel(
    const float* __restrict__ nw)
{
    const int row = blockIdx.x;
    const int tid = threadIdx.x;
    __shared__ float red[256];

    float vals[8];
    float ss = 0.f;
#pragma unroll
    for (int i = 0; i < 8; i++) {
        int c = tid + i * 256;
        float z = g_zx[(size_t)row * DPROJ + c];
        float g = g_y[(size_t)row * DINNER + c] * (z / (1.f + expf(-z)));
        vals[i] = g;
        ss = fmaf(g, g, ss);
    }
    red[tid] = ss;
    __syncthreads();
#pragma unroll
    for (int stride = 128; stride >= 32; stride >>= 1) {
        if (tid < stride) red[tid] += red[tid + stride];
        __syncthreads();
    }
    float total;
    if (tid < 32) {
        float v = red[tid];
#pragma unroll
        for (int o = 16; o > 0; o >>= 1)
            v += __shfl_down_sync(0xffffffffu, v, o);
        if (tid == 0) red[0] = v;
    }
    __syncthreads();
    total = red[0];
    float scale = rsqrtf(total / (float)DINNER + 1e-5f);
#pragma unroll
    for (int i = 0; i < 8; i++) {
        int c = tid + i * 256;
        g_yn[(size_t)row * DINNER + c] = vals[i] * scale * nw[c];
    }
}

// =====================================================================
// launch
// =====================================================================
extern "C" void kernel_launch(void* const* d_in, const int* in_sizes, int n_in,
                              void* d_out, int out_size)
{
    const float* u       = (const float*)d_in[0];
    const float* W_in    = (const float*)d_in[1];
    const float* conv_w  = (const float*)d_in[2];
    const float* conv_b  = (const float*)d_in[3];
    const float* dt_bias = (const float*)d_in[4];
    const float* A_log   = (const float*)d_in[5];
    const float* D_param = (const float*)d_in[6];
    const float* norm_w  = (const float*)d_in[7];
    const float* W_out   = (const float*)d_in[8];
    float* out = (float*)d_out;

    float *zx, *yn;
    cudaGetSymbolAddress((void**)&zx, g_zx);
    cudaGetSymbolAddress((void**)&yn, g_yn);

    // 1) in_proj:  zx[m, e] = sum_d u[m,d] * W_in[e,d]   (M=1024, N=4384, K=1024)
    {
        dim3 grid((DPROJ + BN - 1) / BN, MROWS / BM);
        sgemm_nt<<<grid, 256>>>(u, W_in, zx, MROWS, DPROJ, DMODEL);
    }

    // 2) depthwise conv + silu
    {
        int total = MROWS * CONVD;
        conv_silu_kernel<<<(total + 255) / 256, 256>>>(conv_w, conv_b);
    }

    // 3) SSM scan
    ssm_scan_kernel<<<BATCH * NHEADS, 256>>>(dt_bias, A_log, D_param);

    // 4) gated RMSNorm
    gated_norm_kernel<<<MROWS, 256>>>(norm_w);

    // 5) out_proj: out[m, e] = sum_d yn[m,d] * W_out[e,d]  (M=1024, N=1024, K=2048)
    {
        dim3 grid(DMODEL / BN, MROWS / BM);
        sgemm_nt<<<grid, 256>>>(yn, W_out, out, MROWS, DMODEL, DINNER);
    }
}

// round 2
// speedup vs baseline: 1.6180x; 1.6180x over previous
#include <cuda_runtime.h>
#include <cuda_bf16.h>
#include <math.h>

// ---------------- problem constants ----------------
#define BATCH   2
#define SEQLEN  512
#define DMODEL  1024
#define DINNER  2048
#define NHEADS  32
#define HEADDIM 64
#define DSTATE  128
#define DCONV   4
#define DPROJ   4384   // 2*DINNER + 2*DSTATE + NHEADS
#define CONVD   2304   // DINNER + 2*DSTATE
#define MROWS   (BATCH*SEQLEN)   // 1024
#define DT_OFF  (DINNER + CONVD) // 4352

// ---------------- scratch (static device memory) ----------------
__device__ float g_zx [MROWS * DPROJ];      // in_proj output  (1024 x 4384)
__device__ float g_xbc[MROWS * CONVD];      // conv+silu output (1024 x 2304)
__device__ float g_yp [4][MROWS * DINNER];  // scan partial outputs (n-chunks)
__device__ float g_yn [MROWS * DINNER];     // normed output

// =====================================================================
// SGEMM  C[m,n] = sum_k A[m,k] * B[n,k]   (NT), fp32 with fma.rn.f32x2
// 128x128 tile, BK=16, 256 threads, 8x8 per thread, double-buffered smem.
// gridDim.z = K-splits; accum=1 -> atomicAdd epilogue (C must be zeroed).
// =====================================================================
#define BM 128
#define BN 128
#define BK 16

__global__ __launch_bounds__(256) void sgemm_nt_x2(
    const float* __restrict__ A, const float* __restrict__ Bm,
    float* __restrict__ C, int M, int N, int K, int accum)
{
    __shared__ float As[2][BK][BM];
    __shared__ float Bs[2][BK][BN];

    const int tid = threadIdx.x;
    const int m0 = blockIdx.y * BM;
    const int n0 = blockIdx.x * BN;
    const int kslice = K / gridDim.z;
    const int kbeg = blockIdx.z * kslice;

    const int tm = (tid >> 4) * 8;
    const int tn = (tid & 15) * 8;

    // load mapping: 512 float4 per matrix per stage; 2 per thread
    const int lrow = tid >> 2;          // 0..63 (second load: +64)
    const int lkq  = (tid & 3) * 4;     // 0,4,8,12

    const float* Abase = A  + (size_t)(m0) * K + kbeg;
    const float* Bbase = Bm + (size_t)(n0) * K + kbeg;
    const bool bok0 = (n0 + lrow)      < N;
    const bool bok1 = (n0 + lrow + 64) < N;

    unsigned long long acc[8][4];
#pragma unroll
    for (int i = 0; i < 8; i++)
#pragma unroll
        for (int j = 0; j < 4; j++) acc[i][j] = 0ULL;

    float4 pa0, pa1, pb0, pb1;
    const float4 zero4 = make_float4(0.f, 0.f, 0.f, 0.f);

#define LOAD_STAGE(S)                                                          \
    {                                                                          \
        int kk = (S) * BK + lkq;                                               \
        pa0 = *reinterpret_cast<const float4*>(Abase + (size_t)lrow * K + kk);        \
        pa1 = *reinterpret_cast<const float4*>(Abase + (size_t)(lrow + 64) * K + kk); \
        pb0 = bok0 ? *reinterpret_cast<const float4*>(Bbase + (size_t)lrow * K + kk) : zero4;        \
        pb1 = bok1 ? *reinterpret_cast<const float4*>(Bbase + (size_t)(lrow + 64) * K + kk) : zero4; \
    }

#define STORE_STAGE(BUF)                                                       \
    {                                                                          \
        As[BUF][lkq + 0][lrow] = pa0.x;  As[BUF][lkq + 1][lrow] = pa0.y;       \
        As[BUF][lkq + 2][lrow] = pa0.z;  As[BUF][lkq + 3][lrow] = pa0.w;       \
        As[BUF][lkq + 0][lrow + 64] = pa1.x;  As[BUF][lkq + 1][lrow + 64] = pa1.y; \
        As[BUF][lkq + 2][lrow + 64] = pa1.z;  As[BUF][lkq + 3][lrow + 64] = pa1.w; \
        Bs[BUF][lkq + 0][lrow] = pb0.x;  Bs[BUF][lkq + 1][lrow] = pb0.y;       \
        Bs[BUF][lkq + 2][lrow] = pb0.z;  Bs[BUF][lkq + 3][lrow] = pb0.w;       \
        Bs[BUF][lkq + 0][lrow + 64] = pb1.x;  Bs[BUF][lkq + 1][lrow + 64] = pb1.y; \
        Bs[BUF][lkq + 2][lrow + 64] = pb1.z;  Bs[BUF][lkq + 3][lrow + 64] = pb1.w; \
    }

#define COMPUTE_STAGE(BUF)                                                     \
    {                                                                          \
        _Pragma("unroll")                                                      \
        for (int k = 0; k < BK; k++) {                                         \
            float4 a0v = *reinterpret_cast<const float4*>(&As[BUF][k][tm]);    \
            float4 a1v = *reinterpret_cast<const float4*>(&As[BUF][k][tm + 4]);\
            const unsigned long long* bp =                                     \
                reinterpret_cast<const unsigned long long*>(&Bs[BUF][k][tn]);  \
            unsigned long long rb0 = bp[0], rb1 = bp[1], rb2 = bp[2], rb3 = bp[3]; \
            float af[8] = {a0v.x, a0v.y, a0v.z, a0v.w, a1v.x, a1v.y, a1v.z, a1v.w}; \
            _Pragma("unroll")                                                  \
            for (int i = 0; i < 8; i++) {                                      \
                unsigned long long ra;                                         \
                asm("mov.b64 %0, {%1, %1};" : "=l"(ra) : "f"(af[i]));          \
                asm("fma.rn.f32x2 %0, %1, %2, %0;" : "+l"(acc[i][0]) : "l"(ra), "l"(rb0)); \
                asm("fma.rn.f32x2 %0, %1, %2, %0;" : "+l"(acc[i][1]) : "l"(ra), "l"(rb1)); \
                asm("fma.rn.f32x2 %0, %1, %2, %0;" : "+l"(acc[i][2]) : "l"(ra), "l"(rb2)); \
                asm("fma.rn.f32x2 %0, %1, %2, %0;" : "+l"(acc[i][3]) : "l"(ra), "l"(rb3)); \
            }                                                                  \
        }                                                                      \
    }

    const int nstages = kslice / BK;
    LOAD_STAGE(0);
    STORE_STAGE(0);
    __syncthreads();

    int buf = 0;
    for (int s = 1; s < nstages; s++) {
        LOAD_STAGE(s);
        COMPUTE_STAGE(buf);
        STORE_STAGE(buf ^ 1);
        __syncthreads();
        buf ^= 1;
    }
    COMPUTE_STAGE(buf);

    // epilogue
#pragma unroll
    for (int i = 0; i < 8; i++) {
        float* crow = C + (size_t)(m0 + tm + i) * N + n0 + tn;
#pragma unroll
        for (int j = 0; j < 4; j++) {
            float vx, vy;
            asm("mov.b64 {%0, %1}, %2;" : "=f"(vx), "=f"(vy) : "l"(acc[i][j]));
            if (n0 + tn + 2 * j + 1 < N) {   // N even; pairs never straddle
                if (accum) {
                    atomicAdd(&crow[2 * j], vx);
                    atomicAdd(&crow[2 * j + 1], vy);
                } else {
                    crow[2 * j]     = vx;
                    crow[2 * j + 1] = vy;
                }
            }
        }
    }
#undef LOAD_STAGE
#undef STORE_STAGE
#undef COMPUTE_STAGE
}

// =====================================================================
// Depthwise causal conv (k=4) + bias + SiLU over the xBC slice of zx
// =====================================================================
__global__ __launch_bounds__(256) void conv_silu_kernel(
    const float* __restrict__ cw, const float* __restrict__ cb)
{
    int idx = blockIdx.x * blockDim.x + threadIdx.x;
    if (idx >= MROWS * CONVD) return;
    int c = idx % CONVD;
    int l = (idx / CONVD) % SEQLEN;
    int b = idx / (CONVD * SEQLEN);

    float acc = cb[c];
    const float* w = cw + c * DCONV;
#pragma unroll
    for (int j = 0; j < DCONV; j++) {
        int ls = l - (DCONV - 1) + j;
        if (ls >= 0)
            acc = fmaf(w[j], g_zx[(size_t)(b * SEQLEN + ls) * DPROJ + DINNER + c], acc);
    }
    g_xbc[idx] = acc / (1.f + expf(-acc));
}

// =====================================================================
// Sequential SSM scan, 4-way state split.
// grid = BATCH*NHEADS*4 blocks; block = 256 threads.
// warp layout: p = wid*8 + (lane&7); sub = lane>>3 -> n = chunk*32+sub*8+i
// warp-shuffle reduction over sub; 1 barrier/step; register prefetch.
// =====================================================================
__global__ __launch_bounds__(256) void ssm_scan_kernel(
    const float* __restrict__ dt_bias, const float* __restrict__ A_log,
    const float* __restrict__ Dp)
{
    const int bh    = blockIdx.x >> 2;
    const int chunk = blockIdx.x & 3;
    const int b = bh >> 5;
    const int h = bh & 31;
    const int tid = threadIdx.x;
    const int lane = tid & 31;
    const int wid = tid >> 5;
    const int p = wid * 8 + (lane & 7);
    const int sub = lane >> 3;
    const int nloc = sub * 8;

    __shared__ float sh[2][128];  // [0:64) x, [64:96) B-chunk, [96:128) C-chunk

    float s[8];
#pragma unroll
    for (int i = 0; i < 8; i++) s[i] = 0.f;

    const float Aval = -expf(A_log[h]);
    const float dtb  = dt_bias[h];
    const float Dv   = Dp[h];

    const float* xbase  = g_xbc + (size_t)b * SEQLEN * CONVD + h * HEADDIM;
    const float* bcbase = g_xbc + (size_t)b * SEQLEN * CONVD + DINNER;
    const float* dtbase = g_zx + (size_t)b * SEQLEN * DPROJ + DT_OFF + h;

    // prefetch step 0
    float pre = 0.f;
    if (tid < 64)       pre = xbase[tid];
    else if (tid < 96)  pre = bcbase[chunk * 32 + (tid - 64)];
    else if (tid < 128) pre = bcbase[128 + chunk * 32 + (tid - 96)];
    float pfdt = dtbase[0];

    for (int l = 0; l < SEQLEN; l++) {
        const int par = l & 1;
        if (tid < 128) sh[par][tid] = pre;
        const float dtr = pfdt + dtb;
        __syncthreads();

        // prefetch l+1 (overlaps with compute below)
        if (l + 1 < SEQLEN) {
            const size_t off = (size_t)(l + 1) * CONVD;
            if (tid < 64)       pre = xbase[off + tid];
            else if (tid < 96)  pre = bcbase[off + chunk * 32 + (tid - 64)];
            else if (tid < 128) pre = bcbase[off + 128 + chunk * 32 + (tid - 96)];
            pfdt = dtbase[(size_t)(l + 1) * DPROJ];
        }

        const float dt = (dtr > 20.f) ? dtr : log1pf(expf(dtr));
        const float dA = expf(dt * Aval);
        const float xv = sh[par][p];
        const float coef = dt * xv;
        float acc = (chunk == 0 && sub == 0) ? Dv * xv : 0.f;

#pragma unroll
        for (int i = 0; i < 8; i++) {
            float Bn = sh[par][64 + nloc + i];
            float Cn = sh[par][96 + nloc + i];
            s[i] = fmaf(s[i], dA, coef * Bn);
            acc = fmaf(s[i], Cn, acc);
        }
        acc += __shfl_xor_sync(0xffffffffu, acc, 8);
        acc += __shfl_xor_sync(0xffffffffu, acc, 16);
        if (sub == 0)
            g_yp[chunk][(size_t)(b * SEQLEN + l) * DINNER + h * HEADDIM + p] = acc;
    }
}

// =====================================================================
// Gated RMSNorm (sums 4 scan partials): yg = y*silu(z); yn = rmsnorm(yg)*w
// =====================================================================
__global__ __launch_bounds__(256) void gated_norm_kernel(
    const float* __restrict__ nw)
{
    const int row = blockIdx.x;
    const int tid = threadIdx.x;
    __shared__ float red[256];

    float vals[8];
    float ss = 0.f;
#pragma unroll
    for (int i = 0; i < 8; i++) {
        int c = tid + i * 256;
        size_t idx = (size_t)row * DINNER + c;
        float z = g_zx[(size_t)row * DPROJ + c];
        float yv = g_yp[0][idx] + g_yp[1][idx] + g_yp[2][idx] + g_yp[3][idx];
        float g = yv * (z / (1.f + expf(-z)));
        vals[i] = g;
        ss = fmaf(g, g, ss);
    }
    red[tid] = ss;
    __syncthreads();
#pragma unroll
    for (int stride = 128; stride >= 32; stride >>= 1) {
        if (tid < stride) red[tid] += red[tid + stride];
        __syncthreads();
    }
    if (tid < 32) {
        float v = red[tid];
#pragma unroll
        for (int o = 16; o > 0; o >>= 1)
            v += __shfl_down_sync(0xffffffffu, v, o);
        if (tid == 0) red[0] = v;
    }
    __syncthreads();
    const float scale = rsqrtf(red[0] / (float)DINNER + 1e-5f);
#pragma unroll
    for (int i = 0; i < 8; i++) {
        int c = tid + i * 256;
        g_yn[(size_t)row * DINNER + c] = vals[i] * scale * nw[c];
    }
}

// =====================================================================
// launch
// =====================================================================
extern "C" void kernel_launch(void* const* d_in, const int* in_sizes, int n_in,
                              void* d_out, int out_size)
{
    const float* u       = (const float*)d_in[0];
    const float* W_in    = (const float*)d_in[1];
    const float* conv_w  = (const float*)d_in[2];
    const float* conv_b  = (const float*)d_in[3];
    const float* dt_bias = (const float*)d_in[4];
    const float* A_log   = (const float*)d_in[5];
    const float* D_param = (const float*)d_in[6];
    const float* norm_w  = (const float*)d_in[7];
    const float* W_out   = (const float*)d_in[8];
    float* out = (float*)d_out;

    float *zx, *yn;
    cudaGetSymbolAddress((void**)&zx, g_zx);
    cudaGetSymbolAddress((void**)&yn, g_yn);

    // 1) in_proj: (M=1024, N=4384, K=1024)
    {
        dim3 grid((DPROJ + BN - 1) / BN, MROWS / BM, 1);
        sgemm_nt_x2<<<grid, 256>>>(u, W_in, zx, MROWS, DPROJ, DMODEL, 0);
    }

    // 2) depthwise conv + silu
    {
        int total = MROWS * CONVD;
        conv_silu_kernel<<<(total + 255) / 256, 256>>>(conv_w, conv_b);
    }

    // 3) SSM scan (4-way state split)
    ssm_scan_kernel<<<BATCH * NHEADS * 4, 256>>>(dt_bias, A_log, D_param);

    // 4) gated RMSNorm
    gated_norm_kernel<<<MROWS, 256>>>(norm_w);

    // 5) out_proj: (M=1024, N=1024, K=2048), split-K=2 with atomic epilogue
    cudaMemsetAsync(out, 0, (size_t)out_size * sizeof(float));
    {
        dim3 grid(DMODEL / BN, MROWS / BM, 2);
        sgemm_nt_x2<<<grid, 256>>>(yn, W_out, out, MROWS, DMODEL, DINNER, 1);
    }
}

// round 4
// speedup vs baseline: 2.4273x; 1.5002x over previous
#include <cuda_runtime.h>
#include <cuda_bf16.h>
#include <math.h>
#include <stdint.h>

// ---------------- problem constants ----------------
#define BATCH   2
#define SEQLEN  512
#define DMODEL  1024
#define DINNER  2048
#define NHEADS  32
#define HEADDIM 64
#define DSTATE  128
#define DCONV   4
#define DPROJ   4384   // 2*DINNER + 2*DSTATE + NHEADS
#define NPAD    4480   // DPROJ padded to multiple of 128
#define CONVD   2304   // DINNER + 2*DSTATE
#define MROWS   (BATCH*SEQLEN)   // 1024
#define DT_OFF  (DINNER + CONVD) // 4352

// ---------------- scratch (static device memory) ----------------
__device__ float g_zx [MROWS * DPROJ];      // in_proj output  (1024 x 4384)
__device__ float g_xbc[MROWS * CONVD];      // conv+silu output
__device__ float g_yp [4][MROWS * DINNER];  // scan partial outputs

__device__ __nv_bfloat16 g_uh [MROWS * DMODEL];
__device__ __nv_bfloat16 g_ul [MROWS * DMODEL];
__device__ __nv_bfloat16 g_wih[NPAD  * DMODEL];
__device__ __nv_bfloat16 g_wil[NPAD  * DMODEL];
__device__ __nv_bfloat16 g_ynh[MROWS * DINNER];
__device__ __nv_bfloat16 g_ynl[MROWS * DINNER];
__device__ __nv_bfloat16 g_woh[DMODEL * DINNER];
__device__ __nv_bfloat16 g_wol[DMODEL * DINNER];

// =====================================================================
// helpers
// =====================================================================
__device__ __forceinline__ uint32_t smem_u32(const void* p) {
    uint32_t a;
    asm("{ .reg .u64 t; cvta.to.shared.u64 t, %1; cvt.u32.u64 %0, t; }"
        : "=r"(a) : "l"(p));
    return a;
}

__device__ __forceinline__ void cpa16(uint32_t dst, const void* src) {
    asm volatile("cp.async.cg.shared.global [%0], [%1], 16;"
                 :: "r"(dst), "l"(src) : "memory");
}
#define CP_COMMIT() asm volatile("cp.async.commit_group;" ::: "memory")

__device__ __forceinline__ void ldsm_x4(uint32_t addr, uint32_t& r0, uint32_t& r1,
                                        uint32_t& r2, uint32_t& r3) {
    asm volatile("ldmatrix.sync.aligned.m8n8.x4.shared.b16 {%0,%1,%2,%3}, [%4];"
                 : "=r"(r0), "=r"(r1), "=r"(r2), "=r"(r3) : "r"(addr));
}

__device__ __forceinline__ void mma_bf16(float* c, const uint32_t* a,
                                         uint32_t b0, uint32_t b1) {
    asm volatile(
        "mma.sync.aligned.m16n8k16.row.col.f32.bf16.bf16.f32 "
        "{%0,%1,%2,%3}, {%4,%5,%6,%7}, {%8,%9}, {%0,%1,%2,%3};"
        : "+f"(c[0]), "+f"(c[1]), "+f"(c[2]), "+f"(c[3])
        : "r"(a[0]), "r"(a[1]), "r"(a[2]), "r"(a[3]), "r"(b0), "r"(b1));
}

// =====================================================================
// fp32 -> bf16 hi/lo conversion (zero-pads beyond nsrc)
// =====================================================================
__global__ __launch_bounds__(256) void convert_hilo(
    const float* __restrict__ src, __nv_bfloat16* __restrict__ hi,
    __nv_bfloat16* __restrict__ lo, int nsrc, int ntot)
{
    int i = blockIdx.x * 256 + threadIdx.x;
    if (i >= ntot) return;
    float v = (i < nsrc) ? src[i] : 0.f;
    __nv_bfloat16 h = __float2bfloat16_rn(v);
    hi[i] = h;
    lo[i] = __float2bfloat16_rn(v - __bfloat162float(h));
}

// =====================================================================
// bf16 hi/lo split GEMM (NT): C[m,n] = sum_k A[m,k]*B[n,k]
//   C = Ah*Bh + Ah*Bl + Al*Bh, fp32 accum via mma.sync.m16n8k16
// block 128x128, 8 warps (2x4), warp tile 64x32, BK=32, cp.async x2 stages.
// gridDim.z = K-splits; accum=1 -> atomicAdd (C pre-zeroed).
// =====================================================================
#define GS_ROWB 80        // smem row stride in bytes (32 bf16 + 16B pad)
#define GS_ARRB (128*GS_ROWB)      // 10240 B per tile array
#define GS_STGB (4*GS_ARRB)        // Ah,Al,Bh,Bl per stage
#define GS_SMEM (2*GS_STGB)        // 81920 B

__global__ __launch_bounds__(256, 1) void gemm_bf16_hilo(
    const __nv_bfloat16* __restrict__ Ah, const __nv_bfloat16* __restrict__ Al,
    const __nv_bfloat16* __restrict__ Bh, const __nv_bfloat16* __restrict__ Bl,
    float* __restrict__ C, int M, int N, int K, int accum)
{
    extern __shared__ char smem[];
    const uint32_t sbase = smem_u32(smem);
    const int tid = threadIdx.x;
    const int lane = tid & 31;
    const int warp = tid >> 5;
    const int wm = (warp >> 2) * 64;   // 0 or 64
    const int wn = (warp & 3) * 32;    // 0,32,64,96

    const int m0 = blockIdx.y * 128;
    const int n0 = blockIdx.x * 128;
    const int kslice = K / gridDim.z;
    const int kbeg = blockIdx.z * kslice;
    const int T = kslice / 32;

    float acc[4][4][4];
#pragma unroll
    for (int i = 0; i < 4; i++)
#pragma unroll
        for (int j = 0; j < 4; j++)
#pragma unroll
            for (int q = 0; q < 4; q++) acc[i][j][q] = 0.f;

    // ---- cp.async stage fill: 512 16B chunks per array, 2 per thread ----
    const int c0row = tid >> 1;            // chunk0: row 0..127 (seg 0/1)
    const int c0seg = tid & 1;
    const int c1row = c0row;               // chunk1: seg 2/3
    const int c1seg = c0seg + 2;

#define FILL_STAGE(SB, K0)                                                     \
    {                                                                          \
        const __nv_bfloat16* aph = Ah + (size_t)(m0 + c0row) * K + (K0);       \
        const __nv_bfloat16* apl = Al + (size_t)(m0 + c0row) * K + (K0);       \
        const __nv_bfloat16* bph = Bh + (size_t)(n0 + c0row) * K + (K0);       \
        const __nv_bfloat16* bpl = Bl + (size_t)(n0 + c0row) * K + (K0);       \
        uint32_t drow = sbase + (SB) + c0row * GS_ROWB;                        \
        cpa16(drow + 0 * GS_ARRB + c0seg * 16, aph + c0seg * 8);               \
        cpa16(drow + 1 * GS_ARRB + c0seg * 16, apl + c0seg * 8);               \
        cpa16(drow + 2 * GS_ARRB + c0seg * 16, bph + c0seg * 8);               \
        cpa16(drow + 3 * GS_ARRB + c0seg * 16, bpl + c0seg * 8);               \
        cpa16(drow + 0 * GS_ARRB + c1seg * 16, aph + c1seg * 8);               \
        cpa16(drow + 1 * GS_ARRB + c1seg * 16, apl + c1seg * 8);               \
        cpa16(drow + 2 * GS_ARRB + c1seg * 16, bph + c1seg * 8);               \
        cpa16(drow + 3 * GS_ARRB + c1seg * 16, bpl + c1seg * 8);               \
    }

    // ldmatrix addresses (within a stage, byte offsets added per use)
    const uint32_t a_off = (uint32_t)((wm + (lane & 15)) * GS_ROWB + (lane >> 4) * 16);
    const uint32_t b_row = (uint32_t)(wn + ((lane >> 4) << 3) + (lane & 7));
    const uint32_t b_off = b_row * GS_ROWB + (((lane >> 3) & 1) << 4);

    FILL_STAGE(0, kbeg);
    CP_COMMIT();

    for (int t = 0; t < T; t++) {
        if (t + 1 < T) {
            FILL_STAGE(((t + 1) & 1) * GS_STGB, kbeg + (t + 1) * 32);
            CP_COMMIT();
            asm volatile("cp.async.wait_group 1;" ::: "memory");
        } else {
            asm volatile("cp.async.wait_group 0;" ::: "memory");
        }
        __syncthreads();

        const uint32_t sb = sbase + (t & 1) * GS_STGB;
#pragma unroll
        for (int ks = 0; ks < 2; ks++) {
            const uint32_t kb = ks * 32;   // 16 bf16 = 32 bytes
            uint32_t ah[4][4], al[4][4];
#pragma unroll
            for (int mi = 0; mi < 4; mi++) {
                uint32_t ad = sb + a_off + mi * 16 * GS_ROWB + kb;
                ldsm_x4(ad, ah[mi][0], ah[mi][1], ah[mi][2], ah[mi][3]);
                ldsm_x4(ad + GS_ARRB, al[mi][0], al[mi][1], al[mi][2], al[mi][3]);
            }
            uint32_t bh[2][4], bl[2][4];
#pragma unroll
            for (int bi = 0; bi < 2; bi++) {
                uint32_t bd = sb + 2 * GS_ARRB + b_off + bi * 16 * GS_ROWB + kb;
                ldsm_x4(bd, bh[bi][0], bh[bi][1], bh[bi][2], bh[bi][3]);
                ldsm_x4(bd + GS_ARRB, bl[bi][0], bl[bi][1], bl[bi][2], bl[bi][3]);
            }
#pragma unroll
            for (int mi = 0; mi < 4; mi++) {
#pragma unroll
                for (int ni = 0; ni < 4; ni++) {
                    uint32_t h0 = bh[ni >> 1][(ni & 1) * 2];
                    uint32_t h1 = bh[ni >> 1][(ni & 1) * 2 + 1];
                    uint32_t l0 = bl[ni >> 1][(ni & 1) * 2];
                    uint32_t l1 = bl[ni >> 1][(ni & 1) * 2 + 1];
                    mma_bf16(acc[mi][ni], ah[mi], h0, h1);
                    mma_bf16(acc[mi][ni], ah[mi], l0, l1);
                    mma_bf16(acc[mi][ni], al[mi], h0, h1);
                }
            }
        }
        __syncthreads();
    }

    // ---- epilogue ----
#pragma unroll
    for (int mi = 0; mi < 4; mi++) {
        const int r0 = m0 + wm + mi * 16 + (lane >> 2);
#pragma unroll
        for (int ni = 0; ni < 4; ni++) {
            const int c = n0 + wn + ni * 8 + (lane & 3) * 2;
            if (c < N) {
                float* p0 = C + (size_t)r0 * N + c;
                float* p1 = C + (size_t)(r0 + 8) * N + c;
                if (accum) {
                    atomicAdd(&p0[0], acc[mi][ni][0]);
                    atomicAdd(&p0[1], acc[mi][ni][1]);
                    atomicAdd(&p1[0], acc[mi][ni][2]);
                    atomicAdd(&p1[1], acc[mi][ni][3]);
                } else {
                    p0[0] = acc[mi][ni][0];
                    p0[1] = acc[mi][ni][1];
                    p1[0] = acc[mi][ni][2];
                    p1[1] = acc[mi][ni][3];
                }
            }
        }
    }
#undef FILL_STAGE
}

// =====================================================================
// Depthwise causal conv (k=4) + bias + SiLU over the xBC slice of zx
// =====================================================================
__global__ __launch_bounds__(256) void conv_silu_kernel(
    const float* __restrict__ cw, const float* __restrict__ cb)
{
    int idx = blockIdx.x * blockDim.x + threadIdx.x;
    if (idx >= MROWS * CONVD) return;
    int c = idx % CONVD;
    int l = (idx / CONVD) % SEQLEN;
    int b = idx / (CONVD * SEQLEN);

    float acc = cb[c];
    const float* w = cw + c * DCONV;
#pragma unroll
    for (int j = 0; j < DCONV; j++) {
        int ls = l - (DCONV - 1) + j;
        if (ls >= 0)
            acc = fmaf(w[j], g_zx[(size_t)(b * SEQLEN + ls) * DPROJ + DINNER + c], acc);
    }
    g_xbc[idx] = acc / (1.f + expf(-acc));
}

// =====================================================================
// Sequential SSM scan, 4-way state split (unchanged from R2).
// =====================================================================
__global__ __launch_bounds__(256) void ssm_scan_kernel(
    const float* __restrict__ dt_bias, const float* __restrict__ A_log,
    const float* __restrict__ Dp)
{
    const int bh    = blockIdx.x >> 2;
    const int chunk = blockIdx.x & 3;
    const int b = bh >> 5;
    const int h = bh & 31;
    const int tid = threadIdx.x;
    const int lane = tid & 31;
    const int wid = tid >> 5;
    const int p = wid * 8 + (lane & 7);
    const int sub = lane >> 3;
    const int nloc = sub * 8;

    __shared__ float sh[2][128];

    float s[8];
#pragma unroll
    for (int i = 0; i < 8; i++) s[i] = 0.f;

    const float Aval = -expf(A_log[h]);
    const float dtb  = dt_bias[h];
    const float Dv   = Dp[h];

    const float* xbase  = g_xbc + (size_t)b * SEQLEN * CONVD + h * HEADDIM;
    const float* bcbase = g_xbc + (size_t)b * SEQLEN * CONVD + DINNER;
    const float* dtbase = g_zx + (size_t)b * SEQLEN * DPROJ + DT_OFF + h;

    float pre = 0.f;
    if (tid < 64)       pre = xbase[tid];
    else if (tid < 96)  pre = bcbase[chunk * 32 + (tid - 64)];
    else if (tid < 128) pre = bcbase[128 + chunk * 32 + (tid - 96)];
    float pfdt = dtbase[0];

    for (int l = 0; l < SEQLEN; l++) {
        const int par = l & 1;
        if (tid < 128) sh[par][tid] = pre;
        const float dtr = pfdt + dtb;
        __syncthreads();

        if (l + 1 < SEQLEN) {
            const size_t off = (size_t)(l + 1) * CONVD;
            if (tid < 64)       pre = xbase[off + tid];
            else if (tid < 96)  pre = bcbase[off + chunk * 32 + (tid - 64)];
            else if (tid < 128) pre = bcbase[off + 128 + chunk * 32 + (tid - 96)];
            pfdt = dtbase[(size_t)(l + 1) * DPROJ];
        }

        const float dt = (dtr > 20.f) ? dtr : log1pf(expf(dtr));
        const float dA = expf(dt * Aval);
        const float xv = sh[par][p];
        const float coef = dt * xv;
        float acc = (chunk == 0 && sub == 0) ? Dv * xv : 0.f;

#pragma unroll
        for (int i = 0; i < 8; i++) {
            float Bn = sh[par][64 + nloc + i];
            float Cn = sh[par][96 + nloc + i];
            s[i] = fmaf(s[i], dA, coef * Bn);
            acc = fmaf(s[i], Cn, acc);
        }
        acc += __shfl_xor_sync(0xffffffffu, acc, 8);
        acc += __shfl_xor_sync(0xffffffffu, acc, 16);
        if (sub == 0)
            g_yp[chunk][(size_t)(b * SEQLEN + l) * DINNER + h * HEADDIM + p] = acc;
    }
}

// =====================================================================
// Gated RMSNorm (sums 4 scan partials) -> writes bf16 hi/lo for out_proj
// =====================================================================
__global__ __launch_bounds__(256) void gated_norm_kernel(
    const float* __restrict__ nw)
{
    const int row = blockIdx.x;
    const int tid = threadIdx.x;
    __shared__ float red[256];

    float vals[8];
    float ss = 0.f;
#pragma unroll
    for (int i = 0; i < 8; i++) {
        int c = tid + i * 256;
        size_t idx = (size_t)row * DINNER + c;
        float z = g_zx[(size_t)row * DPROJ + c];
        float yv = g_yp[0][idx] + g_yp[1][idx] + g_yp[2][idx] + g_yp[3][idx];
        float g = yv * (z / (1.f + expf(-z)));
        vals[i] = g;
        ss = fmaf(g, g, ss);
    }
    red[tid] = ss;
    __syncthreads();
#pragma unroll
    for (int stride = 128; stride >= 32; stride >>= 1) {
        if (tid < stride) red[tid] += red[tid + stride];
        __syncthreads();
    }
    if (tid < 32) {
        float v = red[tid];
#pragma unroll
        for (int o = 16; o > 0; o >>= 1)
            v += __shfl_down_sync(0xffffffffu, v, o);
        if (tid == 0) red[0] = v;
    }
    __syncthreads();
    const float scale = rsqrtf(red[0] / (float)DINNER + 1e-5f);
#pragma unroll
    for (int i = 0; i < 8; i++) {
        int c = tid + i * 256;
        size_t idx = (size_t)row * DINNER + c;
        float v = vals[i] * scale * nw[c];
        __nv_bfloat16 h = __float2bfloat16_rn(v);
        g_ynh[idx] = h;
        g_ynl[idx] = __float2bfloat16_rn(v - __bfloat162float(h));
    }
}

// =====================================================================
// launch
// =====================================================================
extern "C" void kernel_launch(void* const* d_in, const int* in_sizes, int n_in,
                              void* d_out, int out_size)
{
    const float* u       = (const float*)d_in[0];
    const float* W_in    = (const float*)d_in[1];
    const float* conv_w  = (const float*)d_in[2];
    const float* conv_b  = (const float*)d_in[3];
    const float* dt_bias = (const float*)d_in[4];
    const float* A_log   = (const float*)d_in[5];
    const float* D_param = (const float*)d_in[6];
    const float* norm_w  = (const float*)d_in[7];
    const float* W_out   = (const float*)d_in[8];
    float* out = (float*)d_out;

    float* zx;
    cudaGetSymbolAddress((void**)&zx, g_zx);
    __nv_bfloat16 *uh, *ul, *wih, *wil, *ynh, *ynl, *woh, *wol;
    cudaGetSymbolAddress((void**)&uh,  g_uh);
    cudaGetSymbolAddress((void**)&ul,  g_ul);
    cudaGetSymbolAddress((void**)&wih, g_wih);
    cudaGetSymbolAddress((void**)&wil, g_wil);
    cudaGetSymbolAddress((void**)&ynh, g_ynh);
    cudaGetSymbolAddress((void**)&ynl, g_ynl);
    cudaGetSymbolAddress((void**)&woh, g_woh);
    cudaGetSymbolAddress((void**)&wol, g_wol);

    cudaFuncSetAttribute(gemm_bf16_hilo,
                         cudaFuncAttributeMaxDynamicSharedMemorySize, GS_SMEM);

    // 0) conversions
    {
        int n = MROWS * DMODEL;
        convert_hilo<<<(n + 255) / 256, 256>>>(u, uh, ul, n, n);
        int nt = NPAD * DMODEL, ns = DPROJ * DMODEL;
        convert_hilo<<<(nt + 255) / 256, 256>>>(W_in, wih, wil, ns, nt);
        int nw2 = DMODEL * DINNER;
        convert_hilo<<<(nw2 + 255) / 256, 256>>>(W_out, woh, wol, nw2, nw2);
    }

    // 1) in_proj: (M=1024, N=4384 (pad 4480), K=1024)
    {
        dim3 grid(NPAD / 128, MROWS / 128, 1);
        gemm_bf16_hilo<<<grid, 256, GS_SMEM>>>(uh, ul, wih, wil, zx,
                                               MROWS, DPROJ, DMODEL, 0);
    }

    // 2) depthwise conv + silu
    {
        int total = MROWS * CONVD;
        conv_silu_kernel<<<(total + 255) / 256, 256>>>(conv_w, conv_b);
    }

    // 3) SSM scan (4-way state split)
    ssm_scan_kernel<<<BATCH * NHEADS * 4, 256>>>(dt_bias, A_log, D_param);

    // 4) gated RMSNorm (emits bf16 hi/lo)
    gated_norm_kernel<<<MROWS, 256>>>(norm_w);

    // 5) out_proj: (M=1024, N=1024, K=2048), split-K=2 + atomic epilogue
    cudaMemsetAsync(out, 0, (size_t)out_size * sizeof(float));
    {
        dim3 grid(DMODEL / 128, MROWS / 128, 2);
        gemm_bf16_hilo<<<grid, 256, GS_SMEM>>>(ynh, ynl, woh, wol, out,
                                               MROWS, DMODEL, DINNER, 1);
    }
}

// round 5
// speedup vs baseline: 2.7804x; 1.1454x over previous
#include <cuda_runtime.h>
#include <cuda_bf16.h>
#include <math.h>
#include <stdint.h>

// ---------------- problem constants ----------------
#define BATCH   2
#define SEQLEN  512
#define DMODEL  1024
#define DINNER  2048
#define NHEADS  32
#define HEADDIM 64
#define DSTATE  128
#define DCONV   4
#define DPROJ   4384   // 2*DINNER + 2*DSTATE + NHEADS
#define NPAD    4480   // DPROJ padded to multiple of 128
#define CONVD   2304   // DINNER + 2*DSTATE
#define MROWS   (BATCH*SEQLEN)   // 1024
#define DT_OFF  (DINNER + CONVD) // 4352

// ---------------- scratch (static device memory) ----------------
__device__ float g_zx [MROWS * DPROJ];      // in_proj output  (1024 x 4384)
__device__ float g_xbc[MROWS * CONVD];      // conv+silu output
__device__ float g_yp [4][MROWS * DINNER];  // scan partial outputs

__device__ __nv_bfloat16 g_uh [MROWS * DMODEL];
__device__ __nv_bfloat16 g_ul [MROWS * DMODEL];
__device__ __nv_bfloat16 g_wih[NPAD  * DMODEL];
__device__ __nv_bfloat16 g_wil[NPAD  * DMODEL];
__device__ __nv_bfloat16 g_ynh[MROWS * DINNER];
__device__ __nv_bfloat16 g_ynl[MROWS * DINNER];
__device__ __nv_bfloat16 g_woh[DMODEL * DINNER];
__device__ __nv_bfloat16 g_wol[DMODEL * DINNER];

// =====================================================================
// helpers
// =====================================================================
__device__ __forceinline__ uint32_t smem_u32(const void* p) {
    uint32_t a;
    asm("{ .reg .u64 t; cvta.to.shared.u64 t, %1; cvt.u32.u64 %0, t; }"
        : "=r"(a) : "l"(p));
    return a;
}

__device__ __forceinline__ void cpa16(uint32_t dst, const void* src) {
    asm volatile("cp.async.cg.shared.global [%0], [%1], 16;"
                 :: "r"(dst), "l"(src) : "memory");
}
#define CP_COMMIT() asm volatile("cp.async.commit_group;" ::: "memory")

__device__ __forceinline__ void ldsm_x4(uint32_t addr, uint32_t& r0, uint32_t& r1,
                                        uint32_t& r2, uint32_t& r3) {
    asm volatile("ldmatrix.sync.aligned.m8n8.x4.shared.b16 {%0,%1,%2,%3}, [%4];"
                 : "=r"(r0), "=r"(r1), "=r"(r2), "=r"(r3) : "r"(addr));
}

__device__ __forceinline__ void mma_bf16(float* c, const uint32_t* a,
                                         uint32_t b0, uint32_t b1) {
    asm volatile(
        "mma.sync.aligned.m16n8k16.row.col.f32.bf16.bf16.f32 "
        "{%0,%1,%2,%3}, {%4,%5,%6,%7}, {%8,%9}, {%0,%1,%2,%3};"
        : "+f"(c[0]), "+f"(c[1]), "+f"(c[2]), "+f"(c[3])
        : "r"(a[0]), "r"(a[1]), "r"(a[2]), "r"(a[3]), "r"(b0), "r"(b1));
}

// =====================================================================
// fp32 -> bf16 hi/lo conversion (zero-pads beyond nsrc)
// =====================================================================
__global__ __launch_bounds__(256) void convert_hilo(
    const float* __restrict__ src, __nv_bfloat16* __restrict__ hi,
    __nv_bfloat16* __restrict__ lo, int nsrc, int ntot)
{
    int i = blockIdx.x * 256 + threadIdx.x;
    if (i >= ntot) return;
    float v = (i < nsrc) ? src[i] : 0.f;
    __nv_bfloat16 h = __float2bfloat16_rn(v);
    hi[i] = h;
    lo[i] = __float2bfloat16_rn(v - __bfloat162float(h));
}

// =====================================================================
// bf16 hi/lo split GEMM (NT): C[m,n] = sum_k A[m,k]*B[n,k]
//   C = Ah*Bh + Ah*Bl + Al*Bh, fp32 accum via mma.sync.m16n8k16
// block 128x128, 8 warps (2x4), warp tile 64x32, BK=32, cp.async x2 stages.
// __launch_bounds__(256,2): 2 CTAs/SM to cover MMA latency.
// gridDim.z = K-splits; accum=1 -> atomicAdd (C pre-zeroed).
// =====================================================================
#define GS_ROWB 80        // smem row stride in bytes (32 bf16 + 16B pad)
#define GS_ARRB (128*GS_ROWB)      // 10240 B per tile array
#define GS_STGB (4*GS_ARRB)        // Ah,Al,Bh,Bl per stage
#define GS_SMEM (2*GS_STGB)        // 81920 B

__global__ __launch_bounds__(256, 2) void gemm_bf16_hilo(
    const __nv_bfloat16* __restrict__ Ah, const __nv_bfloat16* __restrict__ Al,
    const __nv_bfloat16* __restrict__ Bh, const __nv_bfloat16* __restrict__ Bl,
    float* __restrict__ C, int M, int N, int K, int accum)
{
    extern __shared__ char smem[];
    const uint32_t sbase = smem_u32(smem);
    const int tid = threadIdx.x;
    const int lane = tid & 31;
    const int warp = tid >> 5;
    const int wm = (warp >> 2) * 64;   // 0 or 64
    const int wn = (warp & 3) * 32;    // 0,32,64,96

    const int m0 = blockIdx.y * 128;
    const int n0 = blockIdx.x * 128;
    const int kslice = K / gridDim.z;
    const int kbeg = blockIdx.z * kslice;
    const int T = kslice / 32;

    float acc[4][4][4];
#pragma unroll
    for (int i = 0; i < 4; i++)
#pragma unroll
        for (int j = 0; j < 4; j++)
#pragma unroll
            for (int q = 0; q < 4; q++) acc[i][j][q] = 0.f;

    // ---- cp.async stage fill: 512 16B chunks per array, 2 per thread ----
    const int c0row = tid >> 1;            // row 0..127
    const int c0seg = tid & 1;             // seg 0/1, second chunk seg 2/3
    const int c1seg = c0seg + 2;

#define FILL_STAGE(SB, K0)                                                     \
    {                                                                          \
        const __nv_bfloat16* aph = Ah + (size_t)(m0 + c0row) * K + (K0);       \
        const __nv_bfloat16* apl = Al + (size_t)(m0 + c0row) * K + (K0);       \
        const __nv_bfloat16* bph = Bh + (size_t)(n0 + c0row) * K + (K0);       \
        const __nv_bfloat16* bpl = Bl + (size_t)(n0 + c0row) * K + (K0);       \
        uint32_t drow = sbase + (SB) + c0row * GS_ROWB;                        \
        cpa16(drow + 0 * GS_ARRB + c0seg * 16, aph + c0seg * 8);               \
        cpa16(drow + 1 * GS_ARRB + c0seg * 16, apl + c0seg * 8);               \
        cpa16(drow + 2 * GS_ARRB + c0seg * 16, bph + c0seg * 8);               \
        cpa16(drow + 3 * GS_ARRB + c0seg * 16, bpl + c0seg * 8);               \
        cpa16(drow + 0 * GS_ARRB + c1seg * 16, aph + c1seg * 8);               \
        cpa16(drow + 1 * GS_ARRB + c1seg * 16, apl + c1seg * 8);               \
        cpa16(drow + 2 * GS_ARRB + c1seg * 16, bph + c1seg * 8);               \
        cpa16(drow + 3 * GS_ARRB + c1seg * 16, bpl + c1seg * 8);               \
    }

    // ldmatrix addresses (within a stage, byte offsets added per use)
    const uint32_t a_off = (uint32_t)((wm + (lane & 15)) * GS_ROWB + (lane >> 4) * 16);
    const uint32_t b_row = (uint32_t)(wn + ((lane >> 4) << 3) + (lane & 7));
    const uint32_t b_off = b_row * GS_ROWB + (((lane >> 3) & 1) << 4);

    FILL_STAGE(0, kbeg);
    CP_COMMIT();

    for (int t = 0; t < T; t++) {
        if (t + 1 < T) {
            FILL_STAGE(((t + 1) & 1) * GS_STGB, kbeg + (t + 1) * 32);
            CP_COMMIT();
            asm volatile("cp.async.wait_group 1;" ::: "memory");
        } else {
            asm volatile("cp.async.wait_group 0;" ::: "memory");
        }
        __syncthreads();

        const uint32_t sb = sbase + (t & 1) * GS_STGB;
#pragma unroll
        for (int ks = 0; ks < 2; ks++) {
            const uint32_t kb = ks * 32;   // 16 bf16 = 32 bytes
            uint32_t ah[4][4], al[4][4];
#pragma unroll
            for (int mi = 0; mi < 4; mi++) {
                uint32_t ad = sb + a_off + mi * 16 * GS_ROWB + kb;
                ldsm_x4(ad, ah[mi][0], ah[mi][1], ah[mi][2], ah[mi][3]);
                ldsm_x4(ad + GS_ARRB, al[mi][0], al[mi][1], al[mi][2], al[mi][3]);
            }
            uint32_t bh[2][4], bl[2][4];
#pragma unroll
            for (int bi = 0; bi < 2; bi++) {
                uint32_t bd = sb + 2 * GS_ARRB + b_off + bi * 16 * GS_ROWB + kb;
                ldsm_x4(bd, bh[bi][0], bh[bi][1], bh[bi][2], bh[bi][3]);
                ldsm_x4(bd + GS_ARRB, bl[bi][0], bl[bi][1], bl[bi][2], bl[bi][3]);
            }
#pragma unroll
            for (int mi = 0; mi < 4; mi++) {
#pragma unroll
                for (int ni = 0; ni < 4; ni++) {
                    uint32_t h0 = bh[ni >> 1][(ni & 1) * 2];
                    uint32_t h1 = bh[ni >> 1][(ni & 1) * 2 + 1];
                    uint32_t l0 = bl[ni >> 1][(ni & 1) * 2];
                    uint32_t l1 = bl[ni >> 1][(ni & 1) * 2 + 1];
                    mma_bf16(acc[mi][ni], ah[mi], h0, h1);
                    mma_bf16(acc[mi][ni], ah[mi], l0, l1);
                    mma_bf16(acc[mi][ni], al[mi], h0, h1);
                }
            }
        }
        __syncthreads();
    }

    // ---- epilogue ----
#pragma unroll
    for (int mi = 0; mi < 4; mi++) {
        const int r0 = m0 + wm + mi * 16 + (lane >> 2);
#pragma unroll
        for (int ni = 0; ni < 4; ni++) {
            const int c = n0 + wn + ni * 8 + (lane & 3) * 2;
            if (c < N) {
                float* p0 = C + (size_t)r0 * N + c;
                float* p1 = C + (size_t)(r0 + 8) * N + c;
                if (accum) {
                    atomicAdd(&p0[0], acc[mi][ni][0]);
                    atomicAdd(&p0[1], acc[mi][ni][1]);
                    atomicAdd(&p1[0], acc[mi][ni][2]);
                    atomicAdd(&p1[1], acc[mi][ni][3]);
                } else {
                    p0[0] = acc[mi][ni][0];
                    p0[1] = acc[mi][ni][1];
                    p1[0] = acc[mi][ni][2];
                    p1[1] = acc[mi][ni][3];
                }
            }
        }
    }
#undef FILL_STAGE
}

// =====================================================================
// Depthwise causal conv (k=4) + bias + SiLU over the xBC slice of zx
// =====================================================================
__global__ __launch_bounds__(256) void conv_silu_kernel(
    const float* __restrict__ cw, const float* __restrict__ cb)
{
    int idx = blockIdx.x * blockDim.x + threadIdx.x;
    if (idx >= MROWS * CONVD) return;
    int c = idx % CONVD;
    int l = (idx / CONVD) % SEQLEN;
    int b = idx / (CONVD * SEQLEN);

    float acc = cb[c];
    const float* w = cw + c * DCONV;
#pragma unroll
    for (int j = 0; j < DCONV; j++) {
        int ls = l - (DCONV - 1) + j;
        if (ls >= 0)
            acc = fmaf(w[j], g_zx[(size_t)(b * SEQLEN + ls) * DPROJ + DINNER + c], acc);
    }
    g_xbc[idx] = acc / (1.f + expf(-acc));
}

// =====================================================================
// Sequential SSM scan, 4-way state split, 4-step grouped prefetch.
// grid = BATCH*NHEADS*4; block = 256.
// Per group of 4 steps: 1 barrier, 2 gmem loads per thread (MLP>=2).
// =====================================================================
__global__ __launch_bounds__(256) void ssm_scan_kernel(
    const float* __restrict__ dt_bias, const float* __restrict__ A_log,
    const float* __restrict__ Dp)
{
    const int bh    = blockIdx.x >> 2;
    const int chunk = blockIdx.x & 3;
    const int b = bh >> 5;
    const int h = bh & 31;
    const int tid = threadIdx.x;
    const int lane = tid & 31;
    const int wid = tid >> 5;
    const int p = wid * 8 + (lane & 7);
    const int sub = lane >> 3;
    const int nloc = sub * 8;

    __shared__ float sh[2][4][128];
    __shared__ float sh_dt[2][4];

    float s[8];
#pragma unroll
    for (int i = 0; i < 8; i++) s[i] = 0.f;

    const float Aval = -expf(A_log[h]);
    const float dtb  = dt_bias[h];
    const float Dv   = Dp[h];

    const float* xbase  = g_xbc + (size_t)b * SEQLEN * CONVD + h * HEADDIM;
    const float* bcbase = g_xbc + (size_t)b * SEQLEN * CONVD + DINNER;
    const float* dtbase = g_zx + (size_t)b * SEQLEN * DPROJ + DT_OFF + h;

    // per-thread fixed column pointer
    const int f_idx = tid & 127;
    const int f_s   = tid >> 7;      // 0 or 1; also covers f_s+2
    const float* colptr;
    if (f_idx < 64)       colptr = xbase + f_idx;
    else if (f_idx < 96)  colptr = bcbase + chunk * 32 + (f_idx - 64);
    else                  colptr = bcbase + 128 + chunk * 32 + (f_idx - 96);

    // prefetch group 0
    float pre0 = colptr[(size_t)f_s * CONVD];
    float pre1 = colptr[(size_t)(f_s + 2) * CONVD];
    float predt = (tid < 4) ? dtbase[(size_t)tid * DPROJ] : 0.f;

    float* ybase = g_yp[chunk] + (size_t)b * SEQLEN * DINNER + h * HEADDIM + p;

    for (int g = 0; g < SEQLEN / 4; g++) {
        const int buf = g & 1;
        sh[buf][f_s][f_idx] = pre0;
        sh[buf][f_s + 2][f_idx] = pre1;
        if (tid < 4) sh_dt[buf][tid] = predt;
        __syncthreads();

        // prefetch next group (consumed after next barrier)
        if (g + 1 < SEQLEN / 4) {
            const size_t l0 = (size_t)(g + 1) * 4;
            pre0 = colptr[(l0 + f_s) * CONVD];
            pre1 = colptr[(l0 + f_s + 2) * CONVD];
            if (tid < 4) predt = dtbase[(l0 + tid) * DPROJ];
        }

#pragma unroll
        for (int q = 0; q < 4; q++) {
            const float dtr = sh_dt[buf][q] + dtb;
            const float dt = (dtr > 20.f) ? dtr : log1pf(expf(dtr));
            const float dA = expf(dt * Aval);
            const float xv = sh[buf][q][p];
            const float coef = dt * xv;
            float acc = (chunk == 0 && sub == 0) ? Dv * xv : 0.f;

#pragma unroll
            for (int i = 0; i < 8; i++) {
                float Bn = sh[buf][q][64 + nloc + i];
                float Cn = sh[buf][q][96 + nloc + i];
                s[i] = fmaf(s[i], dA, coef * Bn);
                acc = fmaf(s[i], Cn, acc);
            }
            acc += __shfl_xor_sync(0xffffffffu, acc, 8);
            acc += __shfl_xor_sync(0xffffffffu, acc, 16);
            if (sub == 0)
                ybase[(size_t)(g * 4 + q) * DINNER] = acc;
        }
    }
}

// =====================================================================
// Gated RMSNorm (sums 4 scan partials) -> writes bf16 hi/lo for out_proj
// =====================================================================
__global__ __launch_bounds__(256) void gated_norm_kernel(
    const float* __restrict__ nw)
{
    const int row = blockIdx.x;
    const int tid = threadIdx.x;
    __shared__ float red[256];

    float vals[8];
    float ss = 0.f;
#pragma unroll
    for (int i = 0; i < 8; i++) {
        int c = tid + i * 256;
        size_t idx = (size_t)row * DINNER + c;
        float z = g_zx[(size_t)row * DPROJ + c];
        float yv = g_yp[0][idx] + g_yp[1][idx] + g_yp[2][idx] + g_yp[3][idx];
        float g = yv * (z / (1.f + expf(-z)));
        vals[i] = g;
        ss = fmaf(g, g, ss);
    }
    red[tid] = ss;
    __syncthreads();
#pragma unroll
    for (int stride = 128; stride >= 32; stride >>= 1) {
        if (tid < stride) red[tid] += red[tid + stride];
        __syncthreads();
    }
    if (tid < 32) {
        float v = red[tid];
#pragma unroll
        for (int o = 16; o > 0; o >>= 1)
            v += __shfl_down_sync(0xffffffffu, v, o);
        if (tid == 0) red[0] = v;
    }
    __syncthreads();
    const float scale = rsqrtf(red[0] / (float)DINNER + 1e-5f);
#pragma unroll
    for (int i = 0; i < 8; i++) {
        int c = tid + i * 256;
        size_t idx = (size_t)row * DINNER + c;
        float v = vals[i] * scale * nw[c];
        __nv_bfloat16 h = __float2bfloat16_rn(v);
        g_ynh[idx] = h;
        g_ynl[idx] = __float2bfloat16_rn(v - __bfloat162float(h));
    }
}

// =====================================================================
// launch
// =====================================================================
extern "C" void kernel_launch(void* const* d_in, const int* in_sizes, int n_in,
                              void* d_out, int out_size)
{
    const float* u       = (const float*)d_in[0];
    const float* W_in    = (const float*)d_in[1];
    const float* conv_w  = (const float*)d_in[2];
    const float* conv_b  = (const float*)d_in[3];
    const float* dt_bias = (const float*)d_in[4];
    const float* A_log   = (const float*)d_in[5];
    const float* D_param = (const float*)d_in[6];
    const float* norm_w  = (const float*)d_in[7];
    const float* W_out   = (const float*)d_in[8];
    float* out = (float*)d_out;

    float* zx;
    cudaGetSymbolAddress((void**)&zx, g_zx);
    __nv_bfloat16 *uh, *ul, *wih, *wil, *ynh, *ynl, *woh, *wol;
    cudaGetSymbolAddress((void**)&uh,  g_uh);
    cudaGetSymbolAddress((void**)&ul,  g_ul);
    cudaGetSymbolAddress((void**)&wih, g_wih);
    cudaGetSymbolAddress((void**)&wil, g_wil);
    cudaGetSymbolAddress((void**)&ynh, g_ynh);
    cudaGetSymbolAddress((void**)&ynl, g_ynl);
    cudaGetSymbolAddress((void**)&woh, g_woh);
    cudaGetSymbolAddress((void**)&wol, g_wol);

    cudaFuncSetAttribute(gemm_bf16_hilo,
                         cudaFuncAttributeMaxDynamicSharedMemorySize, GS_SMEM);

    // 0) conversions
    {
        int n = MROWS * DMODEL;
        convert_hilo<<<(n + 255) / 256, 256>>>(u, uh, ul, n, n);
        int nt = NPAD * DMODEL, ns = DPROJ * DMODEL;
        convert_hilo<<<(nt + 255) / 256, 256>>>(W_in, wih, wil, ns, nt);
        int nw2 = DMODEL * DINNER;
        convert_hilo<<<(nw2 + 255) / 256, 256>>>(W_out, woh, wol, nw2, nw2);
    }

    // 1) in_proj: (M=1024, N=4384 (pad 4480), K=1024)
    {
        dim3 grid(NPAD / 128, MROWS / 128, 1);
        gemm_bf16_hilo<<<grid, 256, GS_SMEM>>>(uh, ul, wih, wil, zx,
                                               MROWS, DPROJ, DMODEL, 0);
    }

    // 2) depthwise conv + silu
    {
        int total = MROWS * CONVD;
        conv_silu_kernel<<<(total + 255) / 256, 256>>>(conv_w, conv_b);
    }

    // 3) SSM scan (4-way state split, 4-step groups)
    ssm_scan_kernel<<<BATCH * NHEADS * 4, 256>>>(dt_bias, A_log, D_param);

    // 4) gated RMSNorm (emits bf16 hi/lo)
    gated_norm_kernel<<<MROWS, 256>>>(norm_w);

    // 5) out_proj: (M=1024, N=1024, K=2048), split-K=4 + atomic epilogue
    cudaMemsetAsync(out, 0, (size_t)out_size * sizeof(float));
    {
        dim3 grid(DMODEL / 128, MROWS / 128, 4);
        gemm_bf16_hilo<<<grid, 256, GS_SMEM>>>(ynh, ynl, woh, wol, out,
                                               MROWS, DMODEL, DINNER, 1);
    }
}

// round 6
// speedup vs baseline: 3.2625x; 1.1734x over previous
#include <cuda_runtime.h>
#include <cuda_fp16.h>
#include <math.h>
#include <stdint.h>

// ---------------- problem constants ----------------
#define BATCH   2
#define SEQLEN  512
#define DMODEL  1024
#define DINNER  2048
#define NHEADS  32
#define HEADDIM 64
#define DSTATE  128
#define DCONV   4
#define DPROJ   4384   // 2*DINNER + 2*DSTATE + NHEADS
#define NPAD    4480   // DPROJ padded to multiple of 128
#define CONVD   2304   // DINNER + 2*DSTATE
#define MROWS   (BATCH*SEQLEN)   // 1024
#define DT_OFF  (DINNER + CONVD) // 4352

// ---------------- scratch (static device memory) ----------------
__device__ float g_zx [MROWS * DPROJ];      // in_proj output  (1024 x 4384)
__device__ float g_xbc[MROWS * CONVD];      // conv+silu output
__device__ float g_yp [4][MROWS * DINNER];  // scan partial outputs

__device__ __half g_uh [MROWS * DMODEL];
__device__ __half g_ul [MROWS * DMODEL];
__device__ __half g_wih[NPAD  * DMODEL];
__device__ __half g_ynh[MROWS * DINNER];
__device__ __half g_ynl[MROWS * DINNER];
__device__ __half g_woh[DMODEL * DINNER];

// =====================================================================
// helpers
// =====================================================================
__device__ __forceinline__ uint32_t smem_u32(const void* p) {
    uint32_t a;
    asm("{ .reg .u64 t; cvta.to.shared.u64 t, %1; cvt.u32.u64 %0, t; }"
        : "=r"(a) : "l"(p));
    return a;
}

__device__ __forceinline__ void cpa16(uint32_t dst, const void* src) {
    asm volatile("cp.async.cg.shared.global [%0], [%1], 16;"
                 :: "r"(dst), "l"(src) : "memory");
}
#define CP_COMMIT() asm volatile("cp.async.commit_group;" ::: "memory")

__device__ __forceinline__ void ldsm_x4(uint32_t addr, uint32_t& r0, uint32_t& r1,
                                        uint32_t& r2, uint32_t& r3) {
    asm volatile("ldmatrix.sync.aligned.m8n8.x4.shared.b16 {%0,%1,%2,%3}, [%4];"
                 : "=r"(r0), "=r"(r1), "=r"(r2), "=r"(r3) : "r"(addr));
}

__device__ __forceinline__ void mma_f16(float* c, const uint32_t* a,
                                        uint32_t b0, uint32_t b1) {
    asm volatile(
        "mma.sync.aligned.m16n8k16.row.col.f32.f16.f16.f32 "
        "{%0,%1,%2,%3}, {%4,%5,%6,%7}, {%8,%9}, {%0,%1,%2,%3};"
        : "+f"(c[0]), "+f"(c[1]), "+f"(c[2]), "+f"(c[3])
        : "r"(a[0]), "r"(a[1]), "r"(a[2]), "r"(a[3]), "r"(b0), "r"(b1));
}

// =====================================================================
// fp32 -> fp16 conversions
// =====================================================================
__global__ __launch_bounds__(256) void convert_hilo_h(
    const float* __restrict__ src, __half* __restrict__ hi,
    __half* __restrict__ lo, int n)
{
    int i = blockIdx.x * 256 + threadIdx.x;
    if (i >= n) return;
    float v = src[i];
    __half h = __float2half_rn(v);
    hi[i] = h;
    lo[i] = __float2half_rn(v - __half2float(h));
}

__global__ __launch_bounds__(256) void convert_h(
    const float* __restrict__ src, __half* __restrict__ hi, int nsrc, int ntot)
{
    int i = blockIdx.x * 256 + threadIdx.x;
    if (i >= ntot) return;
    float v = (i < nsrc) ? src[i] : 0.f;
    hi[i] = __float2half_rn(v);
}

// =====================================================================
// fp16 2-term split GEMM (NT): C[m,n] = sum_k A[m,k]*B[n,k]
//   C = Ah*Bh + Al*Bh, fp32 accum via mma.sync.m16n8k16.f16
// block 128x128, 8 warps (2x4), warp tile 64x32, BK=32, cp.async x2 stages.
// gridDim.z = K-splits; accum=1 -> atomicAdd (C pre-zeroed).
// =====================================================================
#define GS_ROWB 80                 // smem row stride (32 fp16 + 16B pad)
#define GS_ARRB (128*GS_ROWB)      // 10240 B per tile array
#define GS_STGB (3*GS_ARRB)        // Ah, Al, Bh per stage (30720)
#define GS_SMEM (2*GS_STGB)        // 61440 B

__global__ __launch_bounds__(256, 2) void gemm_f16_2t(
    const __half* __restrict__ Ah, const __half* __restrict__ Al,
    const __half* __restrict__ Bh,
    float* __restrict__ C, int M, int N, int K, int accum)
{
    extern __shared__ char smem[];
    const uint32_t sbase = smem_u32(smem);
    const int tid = threadIdx.x;
    const int lane = tid & 31;
    const int warp = tid >> 5;
    const int wm = (warp >> 2) * 64;   // 0 or 64
    const int wn = (warp & 3) * 32;    // 0,32,64,96

    const int m0 = blockIdx.y * 128;
    const int n0 = blockIdx.x * 128;
    const int kslice = K / gridDim.z;
    const int kbeg = blockIdx.z * kslice;
    const int T = kslice / 32;

    float acc[4][4][4];
#pragma unroll
    for (int i = 0; i < 4; i++)
#pragma unroll
        for (int j = 0; j < 4; j++)
#pragma unroll
            for (int q = 0; q < 4; q++) acc[i][j][q] = 0.f;

    // ---- cp.async fill: 512 chunks/array, 3 arrays, 6 per thread ----
    const int c0row = tid >> 1;            // row 0..127
    const int c0seg = tid & 1;             // seg 0/1; +2 for second chunk
    const int c1seg = c0seg + 2;

#define FILL_STAGE(SB, K0)                                                     \
    {                                                                          \
        const __half* aph = Ah + (size_t)(m0 + c0row) * K + (K0);              \
        const __half* apl = Al + (size_t)(m0 + c0row) * K + (K0);              \
        const __half* bph = Bh + (size_t)(n0 + c0row) * K + (K0);              \
        uint32_t drow = sbase + (SB) + c0row * GS_ROWB;                        \
        cpa16(drow + 0 * GS_ARRB + c0seg * 16, aph + c0seg * 8);               \
        cpa16(drow + 1 * GS_ARRB + c0seg * 16, apl + c0seg * 8);               \
        cpa16(drow + 2 * GS_ARRB + c0seg * 16, bph + c0seg * 8);               \
        cpa16(drow + 0 * GS_ARRB + c1seg * 16, aph + c1seg * 8);               \
        cpa16(drow + 1 * GS_ARRB + c1seg * 16, apl + c1seg * 8);               \
        cpa16(drow + 2 * GS_ARRB + c1seg * 16, bph + c1seg * 8);               \
    }

    // ldmatrix addresses
    const uint32_t a_off = (uint32_t)((wm + (lane & 15)) * GS_ROWB + (lane >> 4) * 16);
    const uint32_t b_row = (uint32_t)(wn + ((lane >> 4) << 3) + (lane & 7));
    const uint32_t b_off = b_row * GS_ROWB + (((lane >> 3) & 1) << 4);

    FILL_STAGE(0, kbeg);
    CP_COMMIT();

    for (int t = 0; t < T; t++) {
        if (t + 1 < T) {
            FILL_STAGE(((t + 1) & 1) * GS_STGB, kbeg + (t + 1) * 32);
            CP_COMMIT();
            asm volatile("cp.async.wait_group 1;" ::: "memory");
        } else {
            asm volatile("cp.async.wait_group 0;" ::: "memory");
        }
        __syncthreads();

        const uint32_t sb = sbase + (t & 1) * GS_STGB;
#pragma unroll
        for (int ks = 0; ks < 2; ks++) {
            const uint32_t kb = ks * 32;   // 16 fp16 = 32 bytes
            uint32_t ah[4][4], al[4][4];
#pragma unroll
            for (int mi = 0; mi < 4; mi++) {
                uint32_t ad = sb + a_off + mi * 16 * GS_ROWB + kb;
                ldsm_x4(ad, ah[mi][0], ah[mi][1], ah[mi][2], ah[mi][3]);
                ldsm_x4(ad + GS_ARRB, al[mi][0], al[mi][1], al[mi][2], al[mi][3]);
            }
            uint32_t bh[2][4];
#pragma unroll
            for (int bi = 0; bi < 2; bi++) {
                uint32_t bd = sb + 2 * GS_ARRB + b_off + bi * 16 * GS_ROWB + kb;
                ldsm_x4(bd, bh[bi][0], bh[bi][1], bh[bi][2], bh[bi][3]);
            }
#pragma unroll
            for (int mi = 0; mi < 4; mi++) {
#pragma unroll
                for (int ni = 0; ni < 4; ni++) {
                    uint32_t h0 = bh[ni >> 1][(ni & 1) * 2];
                    uint32_t h1 = bh[ni >> 1][(ni & 1) * 2 + 1];
                    mma_f16(acc[mi][ni], ah[mi], h0, h1);
                    mma_f16(acc[mi][ni], al[mi], h0, h1);
                }
            }
        }
        __syncthreads();
    }

    // ---- epilogue ----
#pragma unroll
    for (int mi = 0; mi < 4; mi++) {
        const int r0 = m0 + wm + mi * 16 + (lane >> 2);
#pragma unroll
        for (int ni = 0; ni < 4; ni++) {
            const int c = n0 + wn + ni * 8 + (lane & 3) * 2;
            if (c < N) {
                float* p0 = C + (size_t)r0 * N + c;
                float* p1 = C + (size_t)(r0 + 8) * N + c;
                if (accum) {
                    atomicAdd(&p0[0], acc[mi][ni][0]);
                    atomicAdd(&p0[1], acc[mi][ni][1]);
                    atomicAdd(&p1[0], acc[mi][ni][2]);
                    atomicAdd(&p1[1], acc[mi][ni][3]);
                } else {
                    p0[0] = acc[mi][ni][0];
                    p0[1] = acc[mi][ni][1];
                    p1[0] = acc[mi][ni][2];
                    p1[1] = acc[mi][ni][3];
                }
            }
        }
    }
#undef FILL_STAGE
}

// =====================================================================
// Depthwise causal conv (k=4) + bias + SiLU over the xBC slice of zx
// =====================================================================
__global__ __launch_bounds__(256) void conv_silu_kernel(
    const float* __restrict__ cw, const float* __restrict__ cb)
{
    int idx = blockIdx.x * blockDim.x + threadIdx.x;
    if (idx >= MROWS * CONVD) return;
    int c = idx % CONVD;
    int l = (idx / CONVD) % SEQLEN;
    int b = idx / (CONVD * SEQLEN);

    float acc = cb[c];
    const float* w = cw + c * DCONV;
#pragma unroll
    for (int j = 0; j < DCONV; j++) {
        int ls = l - (DCONV - 1) + j;
        if (ls >= 0)
            acc = fmaf(w[j], g_zx[(size_t)(b * SEQLEN + ls) * DPROJ + DINNER + c], acc);
    }
    g_xbc[idx] = acc / (1.f + expf(-acc));
}

// =====================================================================
// Sequential SSM scan, 4-way state split, 8-step grouped prefetch.
// grid = BATCH*NHEADS*4; block = 256.
// Per group of 8 steps: 1 barrier, 4 gmem loads per thread (MLP=4).
// =====================================================================
#define SGRP 8
__global__ __launch_bounds__(256) void ssm_scan_kernel(
    const float* __restrict__ dt_bias, const float* __restrict__ A_log,
    const float* __restrict__ Dp)
{
    const int bh    = blockIdx.x >> 2;
    const int chunk = blockIdx.x & 3;
    const int b = bh >> 5;
    const int h = bh & 31;
    const int tid = threadIdx.x;
    const int lane = tid & 31;
    const int wid = tid >> 5;
    const int p = wid * 8 + (lane & 7);
    const int sub = lane >> 3;
    const int nloc = sub * 8;

    __shared__ float sh[2][SGRP][128];
    __shared__ float sh_dt[2][SGRP];

    float s[8];
#pragma unroll
    for (int i = 0; i < 8; i++) s[i] = 0.f;

    const float Aval = -expf(A_log[h]);
    const float dtb  = dt_bias[h];
    const float Dv   = Dp[h];

    const float* xbase  = g_xbc + (size_t)b * SEQLEN * CONVD + h * HEADDIM;
    const float* bcbase = g_xbc + (size_t)b * SEQLEN * CONVD + DINNER;
    const float* dtbase = g_zx + (size_t)b * SEQLEN * DPROJ + DT_OFF + h;

    // per-thread fixed column pointer
    const int f_idx = tid & 127;
    const int f_s   = tid >> 7;      // 0 or 1; covers steps f_s, f_s+2, f_s+4, f_s+6
    const float* colptr;
    if (f_idx < 64)       colptr = xbase + f_idx;
    else if (f_idx < 96)  colptr = bcbase + chunk * 32 + (f_idx - 64);
    else                  colptr = bcbase + 128 + chunk * 32 + (f_idx - 96);

    // prefetch group 0
    float pre[4];
#pragma unroll
    for (int q = 0; q < 4; q++)
        pre[q] = colptr[(size_t)(f_s + 2 * q) * CONVD];
    float predt = (tid < SGRP) ? dtbase[(size_t)tid * DPROJ] : 0.f;

    float* ybase = g_yp[chunk] + (size_t)b * SEQLEN * DINNER + h * HEADDIM + p;

    for (int g = 0; g < SEQLEN / SGRP; g++) {
        const int buf = g & 1;
#pragma unroll
        for (int q = 0; q < 4; q++)
            sh[buf][f_s + 2 * q][f_idx] = pre[q];
        if (tid < SGRP) sh_dt[buf][tid] = predt;
        __syncthreads();

        // prefetch next group (consumed after next barrier)
        if (g + 1 < SEQLEN / SGRP) {
            const size_t l0 = (size_t)(g + 1) * SGRP;
#pragma unroll
            for (int q = 0; q < 4; q++)
                pre[q] = colptr[(l0 + f_s + 2 * q) * CONVD];
            if (tid < SGRP) predt = dtbase[(l0 + tid) * DPROJ];
        }

#pragma unroll
        for (int q = 0; q < SGRP; q++) {
            const float dtr = sh_dt[buf][q] + dtb;
            const float dt = (dtr > 20.f) ? dtr : log1pf(expf(dtr));
            const float dA = expf(dt * Aval);
            const float xv = sh[buf][q][p];
            const float coef = dt * xv;
            float acc = (chunk == 0 && sub == 0) ? Dv * xv : 0.f;

#pragma unroll
            for (int i = 0; i < 8; i++) {
                float Bn = sh[buf][q][64 + nloc + i];
                float Cn = sh[buf][q][96 + nloc + i];
                s[i] = fmaf(s[i], dA, coef * Bn);
                acc = fmaf(s[i], Cn, acc);
            }
            acc += __shfl_xor_sync(0xffffffffu, acc, 8);
            acc += __shfl_xor_sync(0xffffffffu, acc, 16);
            if (sub == 0)
                ybase[(size_t)(g * SGRP + q) * DINNER] = acc;
        }
    }
}

// =====================================================================
// Gated RMSNorm (sums 4 scan partials) -> writes fp16 hi/lo for out_proj
// =====================================================================
__global__ __launch_bounds__(256) void gated_norm_kernel(
    const float* __restrict__ nw)
{
    const int row = blockIdx.x;
    const int tid = threadIdx.x;
    __shared__ float red[256];

    float vals[8];
    float ss = 0.f;
#pragma unroll
    for (int i = 0; i < 8; i++) {
        int c = tid + i * 256;
        size_t idx = (size_t)row * DINNER + c;
        float z = g_zx[(size_t)row * DPROJ + c];
        float yv = g_yp[0][idx] + g_yp[1][idx] + g_yp[2][idx] + g_yp[3][idx];
        float g = yv * (z / (1.f + expf(-z)));
        vals[i] = g;
        ss = fmaf(g, g, ss);
    }
    red[tid] = ss;
    __syncthreads();
#pragma unroll
    for (int stride = 128; stride >= 32; stride >>= 1) {
        if (tid < stride) red[tid] += red[tid + stride];
        __syncthreads();
    }
    if (tid < 32) {
        float v = red[tid];
#pragma unroll
        for (int o = 16; o > 0; o >>= 1)
            v += __shfl_down_sync(0xffffffffu, v, o);
        if (tid == 0) red[0] = v;
    }
    __syncthreads();
    const float scale = rsqrtf(red[0] / (float)DINNER + 1e-5f);
#pragma unroll
    for (int i = 0; i < 8; i++) {
        int c = tid + i * 256;
        size_t idx = (size_t)row * DINNER + c;
        float v = vals[i] * scale * nw[c];
        __half h = __float2half_rn(v);
        g_ynh[idx] = h;
        g_ynl[idx] = __float2half_rn(v - __half2float(h));
    }
}

// =====================================================================
// launch
// =====================================================================
extern "C" void kernel_launch(void* const* d_in, const int* in_sizes, int n_in,
                              void* d_out, int out_size)
{
    const float* u       = (const float*)d_in[0];
    const float* W_in    = (const float*)d_in[1];
    const float* conv_w  = (const float*)d_in[2];
    const float* conv_b  = (const float*)d_in[3];
    const float* dt_bias = (const float*)d_in[4];
    const float* A_log   = (const float*)d_in[5];
    const float* D_param = (const float*)d_in[6];
    const float* norm_w  = (const float*)d_in[7];
    const float* W_out   = (const float*)d_in[8];
    float* out = (float*)d_out;

    float* zx;
    cudaGetSymbolAddress((void**)&zx, g_zx);
    __half *uh, *ul, *wih, *ynh, *ynl, *woh;
    cudaGetSymbolAddress((void**)&uh,  g_uh);
    cudaGetSymbolAddress((void**)&ul,  g_ul);
    cudaGetSymbolAddress((void**)&wih, g_wih);
    cudaGetSymbolAddress((void**)&ynh, g_ynh);
    cudaGetSymbolAddress((void**)&ynl, g_ynl);
    cudaGetSymbolAddress((void**)&woh, g_woh);

    cudaFuncSetAttribute(gemm_f16_2t,
                         cudaFuncAttributeMaxDynamicSharedMemorySize, GS_SMEM);

    // 0) conversions
    {
        int n = MROWS * DMODEL;
        convert_hilo_h<<<(n + 255) / 256, 256>>>(u, uh, ul, n);
        int nt = NPAD * DMODEL, ns = DPROJ * DMODEL;
        convert_h<<<(nt + 255) / 256, 256>>>(W_in, wih, ns, nt);
        int nw2 = DMODEL * DINNER;
        convert_h<<<(nw2 + 255) / 256, 256>>>(W_out, woh, nw2, nw2);
    }

    // 1) in_proj: (M=1024, N=4384 (pad 4480), K=1024)
    {
        dim3 grid(NPAD / 128, MROWS / 128, 1);
        gemm_f16_2t<<<grid, 256, GS_SMEM>>>(uh, ul, wih, zx,
                                            MROWS, DPROJ, DMODEL, 0);
    }

    // 2) depthwise conv + silu
    {
        int total = MROWS * CONVD;
        conv_silu_kernel<<<(total + 255) / 256, 256>>>(conv_w, conv_b);
    }

    // 3) SSM scan (4-way state split, 8-step groups)
    ssm_scan_kernel<<<BATCH * NHEADS * 4, 256>>>(dt_bias, A_log, D_param);

    // 4) gated RMSNorm (emits fp16 hi/lo)
    gated_norm_kernel<<<MROWS, 256>>>(norm_w);

    // 5) out_proj: (M=1024, N=1024, K=2048), split-K=4 + atomic epilogue
    cudaMemsetAsync(out, 0, (size_t)out_size * sizeof(float));
    {
        dim3 grid(DMODEL / 128, MROWS / 128, 4);
        gemm_f16_2t<<<grid, 256, GS_SMEM>>>(ynh, ynl, woh, out,
                                            MROWS, DMODEL, DINNER, 1);
    }
}

// round 7
// speedup vs baseline: 3.6950x; 1.1326x over previous
#include <cuda_runtime.h>
#include <cuda_fp16.h>
#include <math.h>
#include <stdint.h>

// ---------------- problem constants ----------------
#define BATCH   2
#define SEQLEN  512
#define DMODEL  1024
#define DINNER  2048
#define NHEADS  32
#define HEADDIM 64
#define DSTATE  128
#define DCONV   4
#define DPROJ   4384   // 2*DINNER + 2*DSTATE + NHEADS
#define NPAD    4480   // DPROJ padded to multiple of 128
#define CONVD   2304   // DINNER + 2*DSTATE
#define MROWS   (BATCH*SEQLEN)   // 1024
#define DT_OFF  (DINNER + CONVD) // 4352

// ---------------- scratch (static device memory) ----------------
__device__ float g_zx [MROWS * DPROJ];      // in_proj output  (1024 x 4384)
__device__ float g_xbc[MROWS * CONVD];      // conv+silu output
__device__ float g_yp [4][MROWS * DINNER];  // scan partial outputs

__device__ __half g_uh [MROWS * DMODEL];
__device__ __half g_ul [MROWS * DMODEL];
__device__ __half g_wih[NPAD  * DMODEL];
__device__ __half g_ynh[MROWS * DINNER];
__device__ __half g_ynl[MROWS * DINNER];
__device__ __half g_woh[DMODEL * DINNER];

// =====================================================================
// helpers
// =====================================================================
__device__ __forceinline__ uint32_t smem_u32(const void* p) {
    uint32_t a;
    asm("{ .reg .u64 t; cvta.to.shared.u64 t, %1; cvt.u32.u64 %0, t; }"
        : "=r"(a) : "l"(p));
    return a;
}

__device__ __forceinline__ void cpa16(uint32_t dst, const void* src) {
    asm volatile("cp.async.cg.shared.global [%0], [%1], 16;"
                 :: "r"(dst), "l"(src) : "memory");
}
#define CP_COMMIT() asm volatile("cp.async.commit_group;" ::: "memory")

__device__ __forceinline__ void ldsm_x4(uint32_t addr, uint32_t& r0, uint32_t& r1,
                                        uint32_t& r2, uint32_t& r3) {
    asm volatile("ldmatrix.sync.aligned.m8n8.x4.shared.b16 {%0,%1,%2,%3}, [%4];"
                 : "=r"(r0), "=r"(r1), "=r"(r2), "=r"(r3) : "r"(addr));
}

__device__ __forceinline__ void mma_f16(float* c, const uint32_t* a,
                                        uint32_t b0, uint32_t b1) {
    asm volatile(
        "mma.sync.aligned.m16n8k16.row.col.f32.f16.f16.f32 "
        "{%0,%1,%2,%3}, {%4,%5,%6,%7}, {%8,%9}, {%0,%1,%2,%3};"
        : "+f"(c[0]), "+f"(c[1]), "+f"(c[2]), "+f"(c[3])
        : "r"(a[0]), "r"(a[1]), "r"(a[2]), "r"(a[3]), "r"(b0), "r"(b1));
}

// =====================================================================
// fp32 -> fp16 conversions
// =====================================================================
__global__ __launch_bounds__(256) void convert_hilo_h(
    const float* __restrict__ src, __half* __restrict__ hi,
    __half* __restrict__ lo, int n)
{
    int i = blockIdx.x * 256 + threadIdx.x;
    if (i >= n) return;
    float v = src[i];
    __half h = __float2half_rn(v);
    hi[i] = h;
    lo[i] = __float2half_rn(v - __half2float(h));
}

__global__ __launch_bounds__(256) void convert_h(
    const float* __restrict__ src, __half* __restrict__ hi, int nsrc, int ntot)
{
    int i = blockIdx.x * 256 + threadIdx.x;
    if (i >= ntot) return;
    float v = (i < nsrc) ? src[i] : 0.f;
    hi[i] = __float2half_rn(v);
}

// =====================================================================
// fp16 2-term split GEMM (NT): C[m,n] = sum_k A[m,k]*B[n,k]
//   C = Ah*Bh + Al*Bh, fp32 accum via mma.sync.m16n8k16.f16
// CTA 128x128, 4 warps (2x2), warp tile 64x64, BK=32, 3-stage cp.async.
// 128 threads/CTA, high per-warp ILP (64 MMA : 12 LDSM per k16-step).
// gridDim.z = K-splits; accum=1 -> atomicAdd (C pre-zeroed).
// Requirements: M%128==0, rows of A and B fully allocated (B up to
// gridDim.x*128 rows); only C columns are bound-checked against N.
// =====================================================================
#define GS_ROWB 80                 // smem row stride (32 fp16 + 16B pad)
#define GS_ARRB (128*GS_ROWB)      // 10240 B per tile array
#define GS_STGB (3*GS_ARRB)        // Ah, Al, Bh per stage (30720)
#define GS_SMEM (3*GS_STGB)        // 3 stages: 92160 B

__global__ __launch_bounds__(128) void gemm_f16_2t(
    const __half* __restrict__ Ah, const __half* __restrict__ Al,
    const __half* __restrict__ Bh,
    float* __restrict__ C, int M, int N, int K, int accum)
{
    extern __shared__ char smem[];
    const uint32_t sbase = smem_u32(smem);
    const int tid = threadIdx.x;
    const int lane = tid & 31;
    const int warp = tid >> 5;
    const int wm = (warp >> 1) * 64;   // 0 or 64
    const int wn = (warp & 1) * 64;    // 0 or 64

    const int m0 = blockIdx.y * 128;
    const int n0 = blockIdx.x * 128;
    const int kslice = K / gridDim.z;
    const int kbeg = blockIdx.z * kslice;
    const int T = kslice / 32;

    float acc[4][8][4];
#pragma unroll
    for (int i = 0; i < 4; i++)
#pragma unroll
        for (int j = 0; j < 8; j++)
#pragma unroll
            for (int q = 0; q < 4; q++) acc[i][j][q] = 0.f;

    // ---- cp.async fill: each thread owns one row (tid) of each array ----
    const __half* aph_base = Ah + (size_t)(m0 + tid) * K + kbeg;
    const __half* apl_base = Al + (size_t)(m0 + tid) * K + kbeg;
    const __half* bph_base = Bh + (size_t)(n0 + tid) * K + kbeg;
    const uint32_t drow_base = sbase + tid * GS_ROWB;

#define FILL_STAGE(STG, KOFF)                                                  \
    {                                                                          \
        uint32_t drow = drow_base + (STG) * GS_STGB;                           \
        _Pragma("unroll")                                                      \
        for (int sg = 0; sg < 4; sg++) {                                       \
            cpa16(drow + 0 * GS_ARRB + sg * 16, aph_base + (KOFF) + sg * 8);   \
            cpa16(drow + 1 * GS_ARRB + sg * 16, apl_base + (KOFF) + sg * 8);   \
            cpa16(drow + 2 * GS_ARRB + sg * 16, bph_base + (KOFF) + sg * 8);   \
        }                                                                      \
    }

    // ldmatrix base offsets
    const uint32_t a_off = (uint32_t)((wm + (lane & 15)) * GS_ROWB + (lane >> 4) * 16);
    const uint32_t b_row = (uint32_t)(wn + ((lane >> 4) << 3) + (lane & 7));
    const uint32_t b_off = b_row * GS_ROWB + (((lane >> 3) & 1) << 4);

    FILL_STAGE(0, 0);
    CP_COMMIT();
    FILL_STAGE(1, 32);
    CP_COMMIT();

    for (int t = 0; t < T; t++) {
        asm volatile("cp.async.wait_group 1;" ::: "memory");
        __syncthreads();
        if (t + 2 < T) {
            int stg = (t + 2) % 3;
            FILL_STAGE(stg, (t + 2) * 32);
            CP_COMMIT();
        }

        const uint32_t sb = sbase + (t % 3) * GS_STGB;
#pragma unroll
        for (int ks = 0; ks < 2; ks++) {
            const uint32_t kb = ks * 32;   // 16 fp16 = 32 bytes
            uint32_t ah[4][4], al[4][4], bh[4][4];
#pragma unroll
            for (int mi = 0; mi < 4; mi++) {
                uint32_t ad = sb + a_off + mi * 16 * GS_ROWB + kb;
                ldsm_x4(ad, ah[mi][0], ah[mi][1], ah[mi][2], ah[mi][3]);
                ldsm_x4(ad + GS_ARRB, al[mi][0], al[mi][1], al[mi][2], al[mi][3]);
            }
#pragma unroll
            for (int bi = 0; bi < 4; bi++) {
                uint32_t bd = sb + 2 * GS_ARRB + b_off + bi * 16 * GS_ROWB + kb;
                ldsm_x4(bd, bh[bi][0], bh[bi][1], bh[bi][2], bh[bi][3]);
            }
            // hi pass (32 independent MMAs), then lo pass
#pragma unroll
            for (int mi = 0; mi < 4; mi++)
#pragma unroll
                for (int ni = 0; ni < 8; ni++)
                    mma_f16(acc[mi][ni], ah[mi],
                            bh[ni >> 1][(ni & 1) * 2], bh[ni >> 1][(ni & 1) * 2 + 1]);
#pragma unroll
            for (int mi = 0; mi < 4; mi++)
#pragma unroll
                for (int ni = 0; ni < 8; ni++)
                    mma_f16(acc[mi][ni], al[mi],
                            bh[ni >> 1][(ni & 1) * 2], bh[ni >> 1][(ni & 1) * 2 + 1]);
        }
    }

    // ---- epilogue ----
#pragma unroll
    for (int mi = 0; mi < 4; mi++) {
        const int r0 = m0 + wm + mi * 16 + (lane >> 2);
#pragma unroll
        for (int ni = 0; ni < 8; ni++) {
            const int c = n0 + wn + ni * 8 + (lane & 3) * 2;
            if (c < N) {
                float* p0 = C + (size_t)r0 * N + c;
                float* p1 = C + (size_t)(r0 + 8) * N + c;
                if (accum) {
                    atomicAdd(&p0[0], acc[mi][ni][0]);
                    atomicAdd(&p0[1], acc[mi][ni][1]);
                    atomicAdd(&p1[0], acc[mi][ni][2]);
                    atomicAdd(&p1[1], acc[mi][ni][3]);
                } else {
                    p0[0] = acc[mi][ni][0];
                    p0[1] = acc[mi][ni][1];
                    p1[0] = acc[mi][ni][2];
                    p1[1] = acc[mi][ni][3];
                }
            }
        }
    }
#undef FILL_STAGE
}

// =====================================================================
// Depthwise causal conv (k=4) + bias + SiLU over the xBC slice of zx
// =====================================================================
__global__ __launch_bounds__(256) void conv_silu_kernel(
    const float* __restrict__ cw, const float* __restrict__ cb)
{
    int idx = blockIdx.x * blockDim.x + threadIdx.x;
    if (idx >= MROWS * CONVD) return;
    int c = idx % CONVD;
    int l = (idx / CONVD) % SEQLEN;
    int b = idx / (CONVD * SEQLEN);

    float acc = cb[c];
    const float* w = cw + c * DCONV;
#pragma unroll
    for (int j = 0; j < DCONV; j++) {
        int ls = l - (DCONV - 1) + j;
        if (ls >= 0)
            acc = fmaf(w[j], g_zx[(size_t)(b * SEQLEN + ls) * DPROJ + DINNER + c], acc);
    }
    g_xbc[idx] = acc / (1.f + expf(-acc));
}

// =====================================================================
// Sequential SSM scan, 4-way state split, 8-step grouped prefetch.
// dt/dA computed once per step by 8 leader threads (softplus+exp off the
// per-step critical path). grid = BATCH*NHEADS*4; block = 256.
// =====================================================================
#define SGRP 8
__global__ __launch_bounds__(256) void ssm_scan_kernel(
    const float* __restrict__ dt_bias, const float* __restrict__ A_log,
    const float* __restrict__ Dp)
{
    const int bh    = blockIdx.x >> 2;
    const int chunk = blockIdx.x & 3;
    const int b = bh >> 5;
    const int h = bh & 31;
    const int tid = threadIdx.x;
    const int lane = tid & 31;
    const int wid = tid >> 5;
    const int p = wid * 8 + (lane & 7);
    const int sub = lane >> 3;
    const int nloc = sub * 8;

    __shared__ float sh[2][SGRP][128];
    __shared__ float sh_dt[2][SGRP];
    __shared__ float sh_dA[2][SGRP];

    float s[8];
#pragma unroll
    for (int i = 0; i < 8; i++) s[i] = 0.f;

    const float Aval = -expf(A_log[h]);
    const float dtb  = dt_bias[h];
    const float Dv   = Dp[h];

    const float* xbase  = g_xbc + (size_t)b * SEQLEN * CONVD + h * HEADDIM;
    const float* bcbase = g_xbc + (size_t)b * SEQLEN * CONVD + DINNER;
    const float* dtbase = g_zx + (size_t)b * SEQLEN * DPROJ + DT_OFF + h;

    // per-thread fixed column pointer
    const int f_idx = tid & 127;
    const int f_s   = tid >> 7;      // 0 or 1; covers steps f_s, f_s+2, f_s+4, f_s+6
    const float* colptr;
    if (f_idx < 64)       colptr = xbase + f_idx;
    else if (f_idx < 96)  colptr = bcbase + chunk * 32 + (f_idx - 64);
    else                  colptr = bcbase + 128 + chunk * 32 + (f_idx - 96);

    // prefetch group 0 (raw values; dt transformed at store time)
    float pre[4];
#pragma unroll
    for (int q = 0; q < 4; q++)
        pre[q] = colptr[(size_t)(f_s + 2 * q) * CONVD];
    float predt = (tid < SGRP) ? dtbase[(size_t)tid * DPROJ] : 0.f;

    float* ybase = g_yp[chunk] + (size_t)b * SEQLEN * DINNER + h * HEADDIM + p;

    for (int g = 0; g < SEQLEN / SGRP; g++) {
        const int buf = g & 1;
#pragma unroll
        for (int q = 0; q < 4; q++)
            sh[buf][f_s + 2 * q][f_idx] = pre[q];
        if (tid < SGRP) {
            const float dtr = predt + dtb;
            const float dtv = (dtr > 20.f) ? dtr : log1pf(expf(dtr));
            sh_dt[buf][tid] = dtv;
            sh_dA[buf][tid] = expf(dtv * Aval);
        }
        __syncthreads();

        // prefetch next group (consumed after next barrier)
        if (g + 1 < SEQLEN / SGRP) {
            const size_t l0 = (size_t)(g + 1) * SGRP;
#pragma unroll
            for (int q = 0; q < 4; q++)
                pre[q] = colptr[(l0 + f_s + 2 * q) * CONVD];
            if (tid < SGRP) predt = dtbase[(l0 + tid) * DPROJ];
        }

#pragma unroll
        for (int q = 0; q < SGRP; q++) {
            const float dt = sh_dt[buf][q];
            const float dA = sh_dA[buf][q];
            const float xv = sh[buf][q][p];
            const float coef = dt * xv;
            float acc0 = 0.f, acc1 = 0.f;

#pragma unroll
            for (int i = 0; i < 8; i += 2) {
                float B0 = sh[buf][q][64 + nloc + i];
                float C0 = sh[buf][q][96 + nloc + i];
                float B1 = sh[buf][q][64 + nloc + i + 1];
                float C1 = sh[buf][q][96 + nloc + i + 1];
                s[i]     = fmaf(s[i],     dA, coef * B0);
                s[i + 1] = fmaf(s[i + 1], dA, coef * B1);
                acc0 = fmaf(s[i],     C0, acc0);
                acc1 = fmaf(s[i + 1], C1, acc1);
            }
            float acc = acc0 + acc1;
            acc += __shfl_xor_sync(0xffffffffu, acc, 8);
            acc += __shfl_xor_sync(0xffffffffu, acc, 16);
            if (sub == 0) {
                if (chunk == 0) acc = fmaf(Dv, xv, acc);
                ybase[(size_t)(g * SGRP + q) * DINNER] = acc;
            }
        }
    }
}

// =====================================================================
// Gated RMSNorm (sums 4 scan partials) -> writes fp16 hi/lo for out_proj
// =====================================================================
__global__ __launch_bounds__(256) void gated_norm_kernel(
    const float* __restrict__ nw)
{
    const int row = blockIdx.x;
    const int tid = threadIdx.x;
    __shared__ float red[256];

    float vals[8];
    float ss = 0.f;
#pragma unroll
    for (int i = 0; i < 8; i++) {
        int c = tid + i * 256;
        size_t idx = (size_t)row * DINNER + c;
        float z = g_zx[(size_t)row * DPROJ + c];
        float yv = g_yp[0][idx] + g_yp[1][idx] + g_yp[2][idx] + g_yp[3][idx];
        float g = yv * (z / (1.f + expf(-z)));
        vals[i] = g;
        ss = fmaf(g, g, ss);
    }
    red[tid] = ss;
    __syncthreads();
#pragma unroll
    for (int stride = 128; stride >= 32; stride >>= 1) {
        if (tid < stride) red[tid] += red[tid + stride];
        __syncthreads();
    }
    if (tid < 32) {
        float v = red[tid];
#pragma unroll
        for (int o = 16; o > 0; o >>= 1)
            v += __shfl_down_sync(0xffffffffu, v, o);
        if (tid == 0) red[0] = v;
    }
    __syncthreads();
    const float scale = rsqrtf(red[0] / (float)DINNER + 1e-5f);
#pragma unroll
    for (int i = 0; i < 8; i++) {
        int c = tid + i * 256;
        size_t idx = (size_t)row * DINNER + c;
        float v = vals[i] * scale * nw[c];
        __half h = __float2half_rn(v);
        g_ynh[idx] = h;
        g_ynl[idx] = __float2half_rn(v - __half2float(h));
    }
}

// =====================================================================
// launch
// =====================================================================
extern "C" void kernel_launch(void* const* d_in, const int* in_sizes, int n_in,
                              void* d_out, int out_size)
{
    const float* u       = (const float*)d_in[0];
    const float* W_in    = (const float*)d_in[1];
    const float* conv_w  = (const float*)d_in[2];
    const float* conv_b  = (const float*)d_in[3];
    const float* dt_bias = (const float*)d_in[4];
    const float* A_log   = (const float*)d_in[5];
    const float* D_param = (const float*)d_in[6];
    const float* norm_w  = (const float*)d_in[7];
    const float* W_out   = (const float*)d_in[8];
    float* out = (float*)d_out;

    float* zx;
    cudaGetSymbolAddress((void**)&zx, g_zx);
    __half *uh, *ul, *wih, *ynh, *ynl, *woh;
    cudaGetSymbolAddress((void**)&uh,  g_uh);
    cudaGetSymbolAddress((void**)&ul,  g_ul);
    cudaGetSymbolAddress((void**)&wih, g_wih);
    cudaGetSymbolAddress((void**)&ynh, g_ynh);
    cudaGetSymbolAddress((void**)&ynl, g_ynl);
    cudaGetSymbolAddress((void**)&woh, g_woh);

    cudaFuncSetAttribute(gemm_f16_2t,
                         cudaFuncAttributeMaxDynamicSharedMemorySize, GS_SMEM);

    // 0) conversions
    {
        int n = MROWS * DMODEL;
        convert_hilo_h<<<(n + 255) / 256, 256>>>(u, uh, ul, n);
        int nt = NPAD * DMODEL, ns = DPROJ * DMODEL;
        convert_h<<<(nt + 255) / 256, 256>>>(W_in, wih, ns, nt);
        int nw2 = DMODEL * DINNER;
        convert_h<<<(nw2 + 255) / 256, 256>>>(W_out, woh, nw2, nw2);
    }

    // 1) in_proj: (M=1024, N=4384 (pad 4480), K=1024)
    {
        dim3 grid(NPAD / 128, MROWS / 128, 1);
        gemm_f16_2t<<<grid, 128, GS_SMEM>>>(uh, ul, wih, zx,
                                            MROWS, DPROJ, DMODEL, 0);
    }

    // 2) depthwise conv + silu
    {
        int total = MROWS * CONVD;
        conv_silu_kernel<<<(total + 255) / 256, 256>>>(conv_w, conv_b);
    }

    // 3) SSM scan (4-way state split, 8-step groups)
    ssm_scan_kernel<<<BATCH * NHEADS * 4, 256>>>(dt_bias, A_log, D_param);

    // 4) gated RMSNorm (emits fp16 hi/lo)
    gated_norm_kernel<<<MROWS, 256>>>(norm_w);

    // 5) out_proj: (M=1024, N=1024, K=2048), split-K=4 + atomic epilogue
    cudaMemsetAsync(out, 0, (size_t)out_size * sizeof(float));
    {
        dim3 grid(DMODEL / 128, MROWS / 128, 4);
        gemm_f16_2t<<<grid, 128, GS_SMEM>>>(ynh, ynl, woh, out,
                                            MROWS, DMODEL, DINNER, 1);
    }
}

// round 8
// speedup vs baseline: 3.9448x; 1.0676x over previous
#include <cuda_runtime.h>
#include <cuda_fp16.h>
#include <math.h>
#include <stdint.h>

// ---------------- problem constants ----------------
#define BATCH   2
#define SEQLEN  512
#define DMODEL  1024
#define DINNER  2048
#define NHEADS  32
#define HEADDIM 64
#define DSTATE  128
#define DCONV   4
#define DPROJ   4384   // 2*DINNER + 2*DSTATE + NHEADS
#define NPAD    4608   // DPROJ padded to multiple of 256
#define CONVD   2304   // DINNER + 2*DSTATE
#define MROWS   (BATCH*SEQLEN)   // 1024
#define DT_OFF  (DINNER + CONVD) // 4352

// ---------------- scratch (static device memory) ----------------
__device__ float g_zx [MROWS * DPROJ];      // in_proj output  (1024 x 4384)
__device__ float g_xbc[MROWS * CONVD];      // conv+silu output
__device__ float g_yp [4][MROWS * DINNER];  // scan partial outputs

__device__ __half g_uh [MROWS * DMODEL];
__device__ __half g_ul [MROWS * DMODEL];
__device__ __half g_wih[NPAD  * DMODEL];
__device__ __half g_ynh[MROWS * DINNER];
__device__ __half g_ynl[MROWS * DINNER];
__device__ __half g_woh[DMODEL * DINNER];

// =====================================================================
// helpers
// =====================================================================
__device__ __forceinline__ uint32_t smem_u32(const void* p) {
    uint32_t a;
    asm("{ .reg .u64 t; cvta.to.shared.u64 t, %1; cvt.u32.u64 %0, t; }"
        : "=r"(a) : "l"(p));
    return a;
}

__device__ __forceinline__ void cpa16(uint32_t dst, const void* src) {
    asm volatile("cp.async.cg.shared.global [%0], [%1], 16;"
                 :: "r"(dst), "l"(src) : "memory");
}
#define CP_COMMIT() asm volatile("cp.async.commit_group;" ::: "memory")

__device__ __forceinline__ void ldsm_x4(uint32_t addr, uint32_t& r0, uint32_t& r1,
                                        uint32_t& r2, uint32_t& r3) {
    asm volatile("ldmatrix.sync.aligned.m8n8.x4.shared.b16 {%0,%1,%2,%3}, [%4];"
                 : "=r"(r0), "=r"(r1), "=r"(r2), "=r"(r3) : "r"(addr));
}

__device__ __forceinline__ void mma_f16(float* c, const uint32_t* a,
                                        uint32_t b0, uint32_t b1) {
    asm volatile(
        "mma.sync.aligned.m16n8k16.row.col.f32.f16.f16.f32 "
        "{%0,%1,%2,%3}, {%4,%5,%6,%7}, {%8,%9}, {%0,%1,%2,%3};"
        : "+f"(c[0]), "+f"(c[1]), "+f"(c[2]), "+f"(c[3])
        : "r"(a[0]), "r"(a[1]), "r"(a[2]), "r"(a[3]), "r"(b0), "r"(b1));
}

// =====================================================================
// fp32 -> fp16 conversions
// =====================================================================
__global__ __launch_bounds__(256) void convert_hilo_h(
    const float* __restrict__ src, __half* __restrict__ hi,
    __half* __restrict__ lo, int n)
{
    int i = blockIdx.x * 256 + threadIdx.x;
    if (i >= n) return;
    float v = src[i];
    __half h = __float2half_rn(v);
    hi[i] = h;
    lo[i] = __float2half_rn(v - __half2float(h));
}

__global__ __launch_bounds__(256) void convert_h(
    const float* __restrict__ src, __half* __restrict__ hi, int nsrc, int ntot)
{
    int i = blockIdx.x * 256 + threadIdx.x;
    if (i >= ntot) return;
    float v = (i < nsrc) ? src[i] : 0.f;
    hi[i] = __float2half_rn(v);
}

// =====================================================================
// fp16 2-term split GEMM (NT): C[m,n] = sum_k A[m,k]*B[n,k]
//   C = Ah*Bh + Al*Bh, fp32 accum via mma.sync.m16n8k16.f16
// CTA 128x256, 8 warps (2x4), warp tile 64x64, BK=32, 3-stage cp.async.
// Per warp per k16-step: 12 LDSM feed 64 MMAs.
// gridDim.z = K-splits; accum=1 -> atomicAdd (C pre-zeroed).
// A rows: M%128==0 fully allocated. B rows allocated to gridDim.x*256.
// C columns bound-checked against N.
// =====================================================================
#define GS_ROWB 80                 // smem row stride (32 fp16 + 16B pad)
#define GS_STGB (512*GS_ROWB)      // Ah(128)+Al(128)+Bh(256) rows = 40960 B
#define GS_SMEM (3*GS_STGB)        // 3 stages: 122880 B
#define GS_AL_OFF (128*GS_ROWB)
#define GS_BH_OFF (256*GS_ROWB)

__global__ __launch_bounds__(256) void gemm_f16_2t(
    const __half* __restrict__ Ah, const __half* __restrict__ Al,
    const __half* __restrict__ Bh,
    float* __restrict__ C, int M, int N, int K, int accum)
{
    extern __shared__ char smem[];
    const uint32_t sbase = smem_u32(smem);
    const int tid = threadIdx.x;
    const int lane = tid & 31;
    const int warp = tid >> 5;
    const int wm = (warp >> 2) * 64;   // 0 or 64
    const int wn = (warp & 3) * 64;    // 0,64,128,192

    const int m0 = blockIdx.y * 128;
    const int n0 = blockIdx.x * 256;
    const int kslice = K / gridDim.z;
    const int kbeg = blockIdx.z * kslice;
    const int T = kslice / 32;

    float acc[4][8][4];
#pragma unroll
    for (int i = 0; i < 4; i++)
#pragma unroll
        for (int j = 0; j < 8; j++)
#pragma unroll
            for (int q = 0; q < 4; q++) acc[i][j][q] = 0.f;

    // ---- cp.async fill: 512 rows/stage; thread owns rows tid and tid+256 ----
    // row r<128: Ah[m0+r]; 128<=r<256: Al[m0+r-128]; 256<=r<512: Bh[n0+r-256]
    const __half* ptr0 = (tid < 128)
        ? Ah + (size_t)(m0 + tid) * K + kbeg
        : Al + (size_t)(m0 + tid - 128) * K + kbeg;
    const __half* ptr1 = Bh + (size_t)(n0 + tid) * K + kbeg;
    const uint32_t srow0 = sbase + tid * GS_ROWB;
    const uint32_t srow1 = sbase + (tid + 256) * GS_ROWB;

#define FILL_STAGE(STG, KOFF)                                                  \
    {                                                                          \
        uint32_t s0 = srow0 + (STG) * GS_STGB;                                 \
        uint32_t s1 = srow1 + (STG) * GS_STGB;                                 \
        _Pragma("unroll")                                                      \
        for (int sg = 0; sg < 4; sg++) {                                       \
            cpa16(s0 + sg * 16, ptr0 + (KOFF) + sg * 8);                       \
            cpa16(s1 + sg * 16, ptr1 + (KOFF) + sg * 8);                       \
        }                                                                      \
    }

    // ldmatrix base offsets
    const uint32_t a_off = (uint32_t)((wm + (lane & 15)) * GS_ROWB + (lane >> 4) * 16);
    const uint32_t b_row = (uint32_t)(wn + ((lane >> 4) << 3) + (lane & 7));
    const uint32_t b_off = GS_BH_OFF + b_row * GS_ROWB + (((lane >> 3) & 1) << 4);

    FILL_STAGE(0, 0);
    CP_COMMIT();
    FILL_STAGE(1, 32);
    CP_COMMIT();

    for (int t = 0; t < T; t++) {
        asm volatile("cp.async.wait_group 1;" ::: "memory");
        __syncthreads();
        if (t + 2 < T) {
            int stg = (t + 2) % 3;
            FILL_STAGE(stg, (t + 2) * 32);
            CP_COMMIT();
        }

        const uint32_t sb = sbase + (t % 3) * GS_STGB;
#pragma unroll
        for (int ks = 0; ks < 2; ks++) {
            const uint32_t kb = ks * 32;   // 16 fp16 = 32 bytes
            uint32_t ah[4][4], al[4][4], bh[4][4];
#pragma unroll
            for (int mi = 0; mi < 4; mi++) {
                uint32_t ad = sb + a_off + mi * 16 * GS_ROWB + kb;
                ldsm_x4(ad, ah[mi][0], ah[mi][1], ah[mi][2], ah[mi][3]);
                ldsm_x4(ad + GS_AL_OFF, al[mi][0], al[mi][1], al[mi][2], al[mi][3]);
            }
#pragma unroll
            for (int bi = 0; bi < 4; bi++) {
                uint32_t bd = sb + b_off + bi * 16 * GS_ROWB + kb;
                ldsm_x4(bd, bh[bi][0], bh[bi][1], bh[bi][2], bh[bi][3]);
            }
            // hi pass (32 independent MMAs), then lo pass
#pragma unroll
            for (int mi = 0; mi < 4; mi++)
#pragma unroll
                for (int ni = 0; ni < 8; ni++)
                    mma_f16(acc[mi][ni], ah[mi],
                            bh[ni >> 1][(ni & 1) * 2], bh[ni >> 1][(ni & 1) * 2 + 1]);
#pragma unroll
            for (int mi = 0; mi < 4; mi++)
#pragma unroll
                for (int ni = 0; ni < 8; ni++)
                    mma_f16(acc[mi][ni], al[mi],
                            bh[ni >> 1][(ni & 1) * 2], bh[ni >> 1][(ni & 1) * 2 + 1]);
        }
    }

    // ---- epilogue ----
#pragma unroll
    for (int mi = 0; mi < 4; mi++) {
        const int r0 = m0 + wm + mi * 16 + (lane >> 2);
#pragma unroll
        for (int ni = 0; ni < 8; ni++) {
            const int c = n0 + wn + ni * 8 + (lane & 3) * 2;
            if (c < N) {
                float* p0 = C + (size_t)r0 * N + c;
                float* p1 = C + (size_t)(r0 + 8) * N + c;
                if (accum) {
                    atomicAdd(&p0[0], acc[mi][ni][0]);
                    atomicAdd(&p0[1], acc[mi][ni][1]);
                    atomicAdd(&p1[0], acc[mi][ni][2]);
                    atomicAdd(&p1[1], acc[mi][ni][3]);
                } else {
                    p0[0] = acc[mi][ni][0];
                    p0[1] = acc[mi][ni][1];
                    p1[0] = acc[mi][ni][2];
                    p1[1] = acc[mi][ni][3];
                }
            }
        }
    }
#undef FILL_STAGE
}

// =====================================================================
// Depthwise causal conv (k=4) + bias + SiLU over the xBC slice of zx
// =====================================================================
__global__ __launch_bounds__(256) void conv_silu_kernel(
    const float* __restrict__ cw, const float* __restrict__ cb)
{
    int idx = blockIdx.x * blockDim.x + threadIdx.x;
    if (idx >= MROWS * CONVD) return;
    int c = idx % CONVD;
    int l = (idx / CONVD) % SEQLEN;
    int b = idx / (CONVD * SEQLEN);

    float acc = cb[c];
    const float* w = cw + c * DCONV;
#pragma unroll
    for (int j = 0; j < DCONV; j++) {
        int ls = l - (DCONV - 1) + j;
        if (ls >= 0)
            acc = fmaf(w[j], g_zx[(size_t)(b * SEQLEN + ls) * DPROJ + DINNER + c], acc);
    }
    g_xbc[idx] = acc / (1.f + expf(-acc));
}

// =====================================================================
// Sequential SSM scan, 4-way state split, 8-step grouped prefetch.
// dt/dA computed once per step by 8 leader threads.
// =====================================================================
#define SGRP 8
__global__ __launch_bounds__(256) void ssm_scan_kernel(
    const float* __restrict__ dt_bias, const float* __restrict__ A_log,
    const float* __restrict__ Dp)
{
    const int bh    = blockIdx.x >> 2;
    const int chunk = blockIdx.x & 3;
    const int b = bh >> 5;
    const int h = bh & 31;
    const int tid = threadIdx.x;
    const int lane = tid & 31;
    const int wid = tid >> 5;
    const int p = wid * 8 + (lane & 7);
    const int sub = lane >> 3;
    const int nloc = sub * 8;

    __shared__ float sh[2][SGRP][128];
    __shared__ float sh_dt[2][SGRP];
    __shared__ float sh_dA[2][SGRP];

    float s[8];
#pragma unroll
    for (int i = 0; i < 8; i++) s[i] = 0.f;

    const float Aval = -expf(A_log[h]);
    const float dtb  = dt_bias[h];
    const float Dv   = Dp[h];

    const float* xbase  = g_xbc + (size_t)b * SEQLEN * CONVD + h * HEADDIM;
    const float* bcbase = g_xbc + (size_t)b * SEQLEN * CONVD + DINNER;
    const float* dtbase = g_zx + (size_t)b * SEQLEN * DPROJ + DT_OFF + h;

    const int f_idx = tid & 127;
    const int f_s   = tid >> 7;
    const float* colptr;
    if (f_idx < 64)       colptr = xbase + f_idx;
    else if (f_idx < 96)  colptr = bcbase + chunk * 32 + (f_idx - 64);
    else                  colptr = bcbase + 128 + chunk * 32 + (f_idx - 96);

    float pre[4];
#pragma unroll
    for (int q = 0; q < 4; q++)
        pre[q] = colptr[(size_t)(f_s + 2 * q) * CONVD];
    float predt = (tid < SGRP) ? dtbase[(size_t)tid * DPROJ] : 0.f;

    float* ybase = g_yp[chunk] + (size_t)b * SEQLEN * DINNER + h * HEADDIM + p;

    for (int g = 0; g < SEQLEN / SGRP; g++) {
        const int buf = g & 1;
#pragma unroll
        for (int q = 0; q < 4; q++)
            sh[buf][f_s + 2 * q][f_idx] = pre[q];
        if (tid < SGRP) {
            const float dtr = predt + dtb;
            const float dtv = (dtr > 20.f) ? dtr : log1pf(expf(dtr));
            sh_dt[buf][tid] = dtv;
            sh_dA[buf][tid] = expf(dtv * Aval);
        }
        __syncthreads();

        if (g + 1 < SEQLEN / SGRP) {
            const size_t l0 = (size_t)(g + 1) * SGRP;
#pragma unroll
            for (int q = 0; q < 4; q++)
                pre[q] = colptr[(l0 + f_s + 2 * q) * CONVD];
            if (tid < SGRP) predt = dtbase[(l0 + tid) * DPROJ];
        }

#pragma unroll
        for (int q = 0; q < SGRP; q++) {
            const float dt = sh_dt[buf][q];
            const float dA = sh_dA[buf][q];
            const float xv = sh[buf][q][p];
            const float coef = dt * xv;
            float acc0 = 0.f, acc1 = 0.f;

#pragma unroll
            for (int i = 0; i < 8; i += 2) {
                float B0 = sh[buf][q][64 + nloc + i];
                float C0 = sh[buf][q][96 + nloc + i];
                float B1 = sh[buf][q][64 + nloc + i + 1];
                float C1 = sh[buf][q][96 + nloc + i + 1];
                s[i]     = fmaf(s[i],     dA, coef * B0);
                s[i + 1] = fmaf(s[i + 1], dA, coef * B1);
                acc0 = fmaf(s[i],     C0, acc0);
                acc1 = fmaf(s[i + 1], C1, acc1);
            }
            float acc = acc0 + acc1;
            acc += __shfl_xor_sync(0xffffffffu, acc, 8);
            acc += __shfl_xor_sync(0xffffffffu, acc, 16);
            if (sub == 0) {
                if (chunk == 0) acc = fmaf(Dv, xv, acc);
                ybase[(size_t)(g * SGRP + q) * DINNER] = acc;
            }
        }
    }
}

// =====================================================================
// Gated RMSNorm (sums 4 scan partials) -> writes fp16 hi/lo for out_proj
// =====================================================================
__global__ __launch_bounds__(256) void gated_norm_kernel(
    const float* __restrict__ nw)
{
    const int row = blockIdx.x;
    const int tid = threadIdx.x;
    __shared__ float red[256];

    float vals[8];
    float ss = 0.f;
#pragma unroll
    for (int i = 0; i < 8; i++) {
        int c = tid + i * 256;
        size_t idx = (size_t)row * DINNER + c;
        float z = g_zx[(size_t)row * DPROJ + c];
        float yv = g_yp[0][idx] + g_yp[1][idx] + g_yp[2][idx] + g_yp[3][idx];
        float g = yv * (z / (1.f + expf(-z)));
        vals[i] = g;
        ss = fmaf(g, g, ss);
    }
    red[tid] = ss;
    __syncthreads();
#pragma unroll
    for (int stride = 128; stride >= 32; stride >>= 1) {
        if (tid < stride) red[tid] += red[tid + stride];
        __syncthreads();
    }
    if (tid < 32) {
        float v = red[tid];
#pragma unroll
        for (int o = 16; o > 0; o >>= 1)
            v += __shfl_down_sync(0xffffffffu, v, o);
        if (tid == 0) red[0] = v;
    }
    __syncthreads();
    const float scale = rsqrtf(red[0] / (float)DINNER + 1e-5f);
#pragma unroll
    for (int i = 0; i < 8; i++) {
        int c = tid + i * 256;
        size_t idx = (size_t)row * DINNER + c;
        float v = vals[i] * scale * nw[c];
        __half h = __float2half_rn(v);
        g_ynh[idx] = h;
        g_ynl[idx] = __float2half_rn(v - __half2float(h));
    }
}

// =====================================================================
// launch
// =====================================================================
extern "C" void kernel_launch(void* const* d_in, const int* in_sizes, int n_in,
                              void* d_out, int out_size)
{
    const float* u       = (const float*)d_in[0];
    const float* W_in    = (const float*)d_in[1];
    const float* conv_w  = (const float*)d_in[2];
    const float* conv_b  = (const float*)d_in[3];
    const float* dt_bias = (const float*)d_in[4];
    const float* A_log   = (const float*)d_in[5];
    const float* D_param = (const float*)d_in[6];
    const float* norm_w  = (const float*)d_in[7];
    const float* W_out   = (const float*)d_in[8];
    float* out = (float*)d_out;

    float* zx;
    cudaGetSymbolAddress((void**)&zx, g_zx);
    __half *uh, *ul, *wih, *ynh, *ynl, *woh;
    cudaGetSymbolAddress((void**)&uh,  g_uh);
    cudaGetSymbolAddress((void**)&ul,  g_ul);
    cudaGetSymbolAddress((void**)&wih, g_wih);
    cudaGetSymbolAddress((void**)&ynh, g_ynh);
    cudaGetSymbolAddress((void**)&ynl, g_ynl);
    cudaGetSymbolAddress((void**)&woh, g_woh);

    cudaFuncSetAttribute(gemm_f16_2t,
                         cudaFuncAttributeMaxDynamicSharedMemorySize, GS_SMEM);

    // 0) conversions
    {
        int n = MROWS * DMODEL;
        convert_hilo_h<<<(n + 255) / 256, 256>>>(u, uh, ul, n);
        int nt = NPAD * DMODEL, ns = DPROJ * DMODEL;
        convert_h<<<(nt + 255) / 256, 256>>>(W_in, wih, ns, nt);
        int nw2 = DMODEL * DINNER;
        convert_h<<<(nw2 + 255) / 256, 256>>>(W_out, woh, nw2, nw2);
    }

    // 1) in_proj: (M=1024, N=4384 (pad 4608), K=1024) -- 18x8 = 144 CTAs
    {
        dim3 grid(NPAD / 256, MROWS / 128, 1);
        gemm_f16_2t<<<grid, 256, GS_SMEM>>>(uh, ul, wih, zx,
                                            MROWS, DPROJ, DMODEL, 0);
    }

    // 2) depthwise conv + silu
    {
        int total = MROWS * CONVD;
        conv_silu_kernel<<<(total + 255) / 256, 256>>>(conv_w, conv_b);
    }

    // 3) SSM scan (4-way state split, 8-step groups)
    ssm_scan_kernel<<<BATCH * NHEADS * 4, 256>>>(dt_bias, A_log, D_param);

    // 4) gated RMSNorm (emits fp16 hi/lo)
    gated_norm_kernel<<<MROWS, 256>>>(norm_w);

    // 5) out_proj: (M=1024, N=1024, K=2048), split-K=4 -- 4x8x4 = 128 CTAs
    cudaMemsetAsync(out, 0, (size_t)out_size * sizeof(float));
    {
        dim3 grid(DMODEL / 256, MROWS / 128, 4);
        gemm_f16_2t<<<grid, 256, GS_SMEM>>>(ynh, ynl, woh, out,
                                            MROWS, DMODEL, DINNER, 1);
    }
}